// round 9
// baseline (speedup 1.0000x reference)
#include <cuda_runtime.h>
#include <math.h>

// Problem constants (fixed by the reference)
constexpr int NN  = 100000;
constexpr int NN1 = 60000;
constexpr int NN2 = 30000;
constexpr int EE  = 1600000;
constexpr int DIN = 128;
constexpr int HH  = 64;

// ---------------- float scratch ----------------
constexpr long long F_HMASK = 0;
constexpr long long F_HNEI1 = F_HMASK + (long long)NN * HH;
constexpr long long F_HNEI2 = F_HNEI1 + (long long)NN1 * HH;
constexpr long long F_SUM1  = F_HNEI2 + (long long)NN2 * HH;
constexpr long long F_SUM2  = F_SUM1 + (long long)NN * HH;
constexpr long long F_TOTAL = F_SUM2 + (long long)NN * HH;

__device__ float g_fscratch[F_TOTAL];

// ---------------- int scratch ----------------
constexpr long long I_DEG1 = 0;
constexpr long long I_DEG2 = I_DEG1 + NN;
constexpr long long I_ROW1 = I_DEG2 + NN;
constexpr long long I_ROW2 = I_ROW1 + NN;
constexpr long long I_CUR1 = I_ROW2 + NN;
constexpr long long I_CUR2 = I_CUR1 + NN;
constexpr long long I_CTR  = I_CUR2 + NN;     // 2 counters, padded
constexpr long long I_EDST1 = I_CTR + 32;
constexpr long long I_EDST2 = I_EDST1 + EE;
constexpr long long I_TOTAL = I_EDST2 + EE;

__device__ int g_iscratch[I_TOTAL];

// ---------------- helpers ----------------
__device__ __forceinline__ float elu1(float x) { return x > 0.f ? x : expm1f(x); }
__device__ __forceinline__ float4 elu4(float4 v) {
    v.x = elu1(v.x); v.y = elu1(v.y); v.z = elu1(v.z); v.w = elu1(v.w);
    return v;
}

// ================= input GEMM (proven): Y = elu(X @ W + b) =================
// 64x64 tile, 256 threads, 4x4 register block per thread. 32KB static smem.
template<int K, bool BIASELU>
__global__ __launch_bounds__(256)
void gemm64_kernel(const float* __restrict__ X, const float* __restrict__ W,
                   const float* __restrict__ b, float* __restrict__ Y, int rows)
{
    constexpr int K4 = K / 4;
    __shared__ float4 Xs[64 * K4];
    __shared__ float4 Wt[64 * K4];

    const int t = threadIdx.x;
    const int rowBase = blockIdx.x * 64;

    const float4* X4 = (const float4*)X;
    for (int idx = t; idx < 64 * K4; idx += 256) {
        int r  = idx / K4;
        int k4 = idx % K4;
        int gr = rowBase + r;
        float4 v = make_float4(0.f, 0.f, 0.f, 0.f);
        if (gr < rows) v = X4[(long long)gr * K4 + k4];
        Xs[idx] = v;
    }
    for (int idx = t; idx < K * 64; idx += 256) {
        int k = idx >> 6;
        int c = idx & 63;
        int k4 = k >> 2, kk = k & 3;
        ((float*)&Wt[c * K4 + (k4 ^ ((c >> 2) & 7))])[kk] = W[idx];
    }
    __syncthreads();

    const int c4  = t & 15;
    const int r0  = (t >> 4) * 4;
    const int swz = c4 & 7;

    float acc[4][4];
#pragma unroll
    for (int i = 0; i < 4; i++)
#pragma unroll
        for (int j = 0; j < 4; j++) acc[i][j] = 0.f;

#pragma unroll 8
    for (int k4 = 0; k4 < K4; k4++) {
        float4 xv[4], wv[4];
#pragma unroll
        for (int i = 0; i < 4; i++) xv[i] = Xs[(r0 + i) * K4 + k4];
#pragma unroll
        for (int j = 0; j < 4; j++) wv[j] = Wt[(c4 * 4 + j) * K4 + (k4 ^ swz)];
#pragma unroll
        for (int i = 0; i < 4; i++)
#pragma unroll
            for (int j = 0; j < 4; j++)
                acc[i][j] += xv[i].x * wv[j].x + xv[i].y * wv[j].y +
                             xv[i].z * wv[j].z + xv[i].w * wv[j].w;
    }

    float4 bias = make_float4(0.f, 0.f, 0.f, 0.f);
    if (BIASELU) bias = ((const float4*)b)[c4];

    float4* Y4 = (float4*)Y;
#pragma unroll
    for (int i = 0; i < 4; i++) {
        int gr = rowBase + r0 + i;
        if (gr < rows) {
            float4 o = make_float4(acc[i][0] + bias.x, acc[i][1] + bias.y,
                                   acc[i][2] + bias.z, acc[i][3] + bias.w);
            if (BIASELU) o = elu4(o);
            Y4[(long long)gr * 16 + c4] = o;
        }
    }
}

// ================= CSR build =================
__global__ __launch_bounds__(256)
void zero_kernel(int* __restrict__ d1, int* __restrict__ d2, int* __restrict__ ctr)
{
    int i = blockIdx.x * 256 + threadIdx.x;
    if (i < NN) { d1[i] = 0; d2[i] = 0; }
    if (i < 2) ctr[i] = 0;
}

// 4 edges per thread via int4 — 4 independent RED chains in flight.
__global__ __launch_bounds__(256)
void hist2_kernel(const int4* __restrict__ src1, const int4* __restrict__ src2,
                  int* __restrict__ deg1, int* __restrict__ deg2)
{
    constexpr int Q = EE / 4;
    int i = blockIdx.x * 256 + threadIdx.x;
    if (i < Q) {
        int4 s = __ldg(src1 + i);
        atomicAdd(deg1 + s.x, 1);
        atomicAdd(deg1 + s.y, 1);
        atomicAdd(deg1 + s.z, 1);
        atomicAdd(deg1 + s.w, 1);
    } else if (i < 2 * Q) {
        int4 s = __ldg(src2 + i - Q);
        atomicAdd(deg2 + s.x, 1);
        atomicAdd(deg2 + s.y, 1);
        atomicAdd(deg2 + s.z, 1);
        atomicAdd(deg2 + s.w, 1);
    }
}

__global__ __launch_bounds__(256)
void base2_kernel(const int* __restrict__ deg1, int* __restrict__ row1, int* __restrict__ cur1,
                  const int* __restrict__ deg2, int* __restrict__ row2, int* __restrict__ cur2,
                  int* __restrict__ ctr, int nb)
{
    __shared__ int warpTot[8];
    __shared__ int blockBase;
    int rel = blockIdx.x >= nb;
    const int* deg = rel ? deg2 : deg1;
    int* rowp = rel ? row2 : row1;
    int* cur  = rel ? cur2 : cur1;
    int* counter = ctr + rel;

    int i = (blockIdx.x - rel * nb) * 256 + threadIdx.x;
    int lane = threadIdx.x & 31;
    int wid  = threadIdx.x >> 5;

    int d = (i < NN) ? deg[i] : 0;
    int x = d;
#pragma unroll
    for (int o = 1; o < 32; o <<= 1) {
        int y = __shfl_up_sync(0xffffffffu, x, o);
        if (lane >= o) x += y;
    }
    if (lane == 31) warpTot[wid] = x;
    __syncthreads();
    if (threadIdx.x == 0) {
        int s = 0;
#pragma unroll
        for (int w = 0; w < 8; w++) { int tw = warpTot[w]; warpTot[w] = s; s += tw; }
        blockBase = atomicAdd(counter, s);
    }
    __syncthreads();
    int base = blockBase + warpTot[wid] + x - d;
    if (i < NN) { rowp[i] = base; cur[i] = base; }
}

// 4 edges per thread via int4 — 4 independent load->atomic->store chains.
__global__ __launch_bounds__(256)
void reorder2_kernel(const int4* __restrict__ src1, const int4* __restrict__ dst1,
                     int* __restrict__ cur1, int* __restrict__ edst1,
                     const int4* __restrict__ src2, const int4* __restrict__ dst2,
                     int* __restrict__ cur2, int* __restrict__ edst2)
{
    constexpr int Q = EE / 4;
    int i = blockIdx.x * 256 + threadIdx.x;
    if (i < Q) {
        int4 s = __ldg(src1 + i);
        int4 d = __ldg(dst1 + i);
        int p0 = atomicAdd(cur1 + s.x, 1);
        int p1 = atomicAdd(cur1 + s.y, 1);
        int p2 = atomicAdd(cur1 + s.z, 1);
        int p3 = atomicAdd(cur1 + s.w, 1);
        edst1[p0] = d.x;
        edst1[p1] = d.y;
        edst1[p2] = d.z;
        edst1[p3] = d.w;
    } else if (i < 2 * Q) {
        i -= Q;
        int4 s = __ldg(src2 + i);
        int4 d = __ldg(dst2 + i);
        int p0 = atomicAdd(cur2 + s.x, 1);
        int p1 = atomicAdd(cur2 + s.y, 1);
        int p2 = atomicAdd(cur2 + s.z, 1);
        int p3 = atomicAdd(cur2 + s.w, 1);
        edst2[p0] = d.x;
        edst2[p1] = d.y;
        edst2[p2] = d.z;
        edst2[p3] = d.w;
    }
}

// ================= aggregate: one warp per node, float4 / half-warp rows =========
// Each half-warp (16 lanes x float4 = 64 floats) covers a full feature row, so a
// warp gathers 2 neighbor rows per load instruction, 8 rows in flight unrolled.
__global__ __launch_bounds__(256)
void agg_kernel(const int* __restrict__ rowptr, const int* __restrict__ deg,
                const int* __restrict__ edst, const float4* __restrict__ hnei,
                float4* __restrict__ sum, int n)
{
    int warp = (blockIdx.x * 256 + threadIdx.x) >> 5;
    int lane = threadIdx.x & 31;
    if (warp >= n) return;
    const int half = lane >> 4;     // 0 or 1
    const int l16  = lane & 15;

    int base = __ldg(rowptr + warp);
    int d    = __ldg(deg + warp);

    float4 acc = make_float4(0.f, 0.f, 0.f, 0.f);
    for (int j0 = 0; j0 < d; j0 += 32) {
        int m = min(32, d - j0);
        int e = 0;
        if (lane < m) e = __ldg(edst + base + j0 + lane);
        int jj = 0;
        for (; jj + 8 <= m; jj += 8) {
            int d0 = __shfl_sync(0xffffffffu, e, jj + half);
            int d1 = __shfl_sync(0xffffffffu, e, jj + 2 + half);
            int d2 = __shfl_sync(0xffffffffu, e, jj + 4 + half);
            int d3 = __shfl_sync(0xffffffffu, e, jj + 6 + half);
            float4 v0 = __ldg(hnei + (long long)d0 * 16 + l16);
            float4 v1 = __ldg(hnei + (long long)d1 * 16 + l16);
            float4 v2 = __ldg(hnei + (long long)d2 * 16 + l16);
            float4 v3 = __ldg(hnei + (long long)d3 * 16 + l16);
            acc.x += v0.x + v1.x + v2.x + v3.x;
            acc.y += v0.y + v1.y + v2.y + v3.y;
            acc.z += v0.z + v1.z + v2.z + v3.z;
            acc.w += v0.w + v1.w + v2.w + v3.w;
        }
        for (; jj + 2 <= m; jj += 2) {
            int dd = __shfl_sync(0xffffffffu, e, jj + half);
            float4 v = __ldg(hnei + (long long)dd * 16 + l16);
            acc.x += v.x; acc.y += v.y; acc.z += v.z; acc.w += v.w;
        }
        if (jj < m) {
            int dd = __shfl_sync(0xffffffffu, e, jj);
            if (half == 0) {
                float4 v = __ldg(hnei + (long long)dd * 16 + l16);
                acc.x += v.x; acc.y += v.y; acc.z += v.z; acc.w += v.w;
            }
        }
    }
    // combine the two half-warp partial sums onto lanes 0-15
    acc.x += __shfl_down_sync(0xffffffffu, acc.x, 16);
    acc.y += __shfl_down_sync(0xffffffffu, acc.y, 16);
    acc.z += __shfl_down_sync(0xffffffffu, acc.z, 16);
    acc.w += __shfl_down_sync(0xffffffffu, acc.w, 16);
    if (half == 0) sum[(long long)warp * 16 + l16] = acc;
}

// ================= fused A-GEMM x2 + epilogue (32KB static smem) =================
__global__ __launch_bounds__(256)
void gemm_epi_kernel(const float* __restrict__ sum1, const float* __restrict__ A0,
                     const float* __restrict__ sum2, const float* __restrict__ A1,
                     const int* __restrict__ deg1, const int* __restrict__ deg2,
                     const float4* __restrict__ hmask, float* __restrict__ out)
{
    constexpr int K4 = HH / 4;           // 16
    __shared__ float4 Xs[64 * K4];       // 16KB
    __shared__ float4 Wt[64 * K4];       // 16KB

    const int t = threadIdx.x;
    const int rowBase = blockIdx.x * 64;
    const int c4  = t & 15;
    const int r0  = (t >> 4) * 4;
    const int swz = c4 & 7;

    float acc1[4][4], acc2[4][4];

    for (int phase = 0; phase < 2; phase++) {
        const float4* X4 = phase ? (const float4*)sum2 : (const float4*)sum1;
        const float* W   = phase ? A1 : A0;
        if (phase) __syncthreads();      // all reads of phase-0 tiles done

#pragma unroll
        for (int it = 0; it < 4; it++) {
            int idx = t + it * 256;      // [0, 1024)
            int r  = idx >> 4;
            int k4 = idx & 15;
            int gr = rowBase + r;
            float4 v = make_float4(0.f, 0.f, 0.f, 0.f);
            if (gr < NN) v = X4[(long long)gr * K4 + k4];
            Xs[idx] = v;
        }
#pragma unroll
        for (int it = 0; it < 16; it++) {
            int idx = t + it * 256;      // [0, 4096)
            int k = idx >> 6;
            int c = idx & 63;
            ((float*)&Wt[c * K4 + ((k >> 2) ^ ((c >> 2) & 7))])[k & 3] = W[idx];
        }
        __syncthreads();

        float (*acc)[4] = phase ? acc2 : acc1;
#pragma unroll
        for (int i = 0; i < 4; i++)
#pragma unroll
            for (int j = 0; j < 4; j++) acc[i][j] = 0.f;

#pragma unroll 4
        for (int k4 = 0; k4 < K4; k4++) {
            float4 xv[4];
#pragma unroll
            for (int i = 0; i < 4; i++) xv[i] = Xs[(r0 + i) * K4 + k4];
#pragma unroll
            for (int j = 0; j < 4; j++) {
                float4 wv = Wt[(c4 * 4 + j) * K4 + (k4 ^ swz)];
#pragma unroll
                for (int i = 0; i < 4; i++)
                    acc[i][j] += xv[i].x * wv.x + xv[i].y * wv.y +
                                 xv[i].z * wv.z + xv[i].w * wv.w;
            }
        }
    }

    // epilogue
    float4* O = (float4*)out;
    const float4* HT = O + 4LL * NN * 16;
#pragma unroll
    for (int i = 0; i < 4; i++) {
        int gr = rowBase + r0 + i;
        if (gr >= NN) continue;
        int d1 = __ldg(deg1 + gr);
        int d2 = __ldg(deg2 + gr);
        float inv1 = d1 > 0 ? 1.f / (float)d1 : 1.f;
        float inv2 = d2 > 0 ? 1.f / (float)d2 : 1.f;
        float4 a1 = make_float4(acc1[i][0] * inv1, acc1[i][1] * inv1,
                                acc1[i][2] * inv1, acc1[i][3] * inv1);
        float4 a2 = make_float4(acc2[i][0] * inv2, acc2[i][1] * inv2,
                                acc2[i][2] * inv2, acc2[i][3] * inv2);
        long long g = (long long)gr * 16 + c4;
        float4 ht = HT[g];
        float4 hm = hmask[g];
        float4 v;
        v = make_float4(ht.x + a1.x, ht.y + a1.y, ht.z + a1.z, ht.w + a1.w);
        O[0LL * NN * 16 + g] = elu4(v);
        v = make_float4(hm.x + a1.x, hm.y + a1.y, hm.z + a1.z, hm.w + a1.w);
        O[1LL * NN * 16 + g] = elu4(v);
        v = make_float4(ht.x + a2.x, ht.y + a2.y, ht.z + a2.z, ht.w + a2.w);
        O[2LL * NN * 16 + g] = elu4(v);
        v = make_float4(hm.x + a2.x, hm.y + a2.y, hm.z + a2.z, hm.w + a2.w);
        O[3LL * NN * 16 + g] = elu4(v);
    }
}

// ================= launch (single stream, no statics, no attribute calls) =========
extern "C" void kernel_launch(void* const* d_in, const int* in_sizes, int n_in,
                              void* d_out, int out_size)
{
    const float* feats0    = (const float*)d_in[0];
    const float* feats1    = (const float*)d_in[1];
    const float* feats2    = (const float*)d_in[2];
    const float* mask_feat = (const float*)d_in[3];
    const int*   src1      = (const int*)d_in[4];
    const int*   dst1      = (const int*)d_in[5];
    const int*   src2      = (const int*)d_in[6];
    const int*   dst2      = (const int*)d_in[7];
    const float* W0        = (const float*)d_in[8];
    const float* b0        = (const float*)d_in[9];
    const float* W1        = (const float*)d_in[10];
    const float* b1        = (const float*)d_in[11];
    const float* W2        = (const float*)d_in[12];
    const float* b2        = (const float*)d_in[13];
    const float* A0        = (const float*)d_in[14];
    const float* A1        = (const float*)d_in[15];

    float* out = (float*)d_out;

    void* fp = nullptr; cudaGetSymbolAddress(&fp, g_fscratch);
    void* ip = nullptr; cudaGetSymbolAddress(&ip, g_iscratch);
    float* F = (float*)fp;
    int*   I = (int*)ip;

    float* hmask = F + F_HMASK;
    float* hnei1 = F + F_HNEI1;
    float* hnei2 = F + F_HNEI2;
    float* sum1  = F + F_SUM1;
    float* sum2  = F + F_SUM2;

    int* deg1 = I + I_DEG1;
    int* deg2 = I + I_DEG2;
    int* row1 = I + I_ROW1;
    int* row2 = I + I_ROW2;
    int* cur1 = I + I_CUR1;
    int* cur2 = I + I_CUR2;
    int* ctr  = I + I_CTR;
    int* edst1 = I + I_EDST1;
    int* edst2 = I + I_EDST2;

    float* htar = out + 4LL * NN * HH;

    auto cdiv = [](long long a, long long b) { return (int)((a + b - 1) / b); };

    const int NB = cdiv(NN, 256);

    // CSR build chain (4 edges/thread in hist + reorder)
    zero_kernel<<<NB, 256>>>(deg1, deg2, ctr);
    hist2_kernel<<<cdiv(2LL * (EE / 4), 256), 256>>>((const int4*)src1, (const int4*)src2,
                                                     deg1, deg2);
    base2_kernel<<<2 * NB, 256>>>(deg1, row1, cur1, deg2, row2, cur2, ctr, NB);
    reorder2_kernel<<<cdiv(2LL * (EE / 4), 256), 256>>>((const int4*)src1, (const int4*)dst1,
                                                        cur1, edst1,
                                                        (const int4*)src2, (const int4*)dst2,
                                                        cur2, edst2);

    // Input GEMMs (+bias +ELU)
    gemm64_kernel<DIN, true><<<cdiv(NN1, 64), 256>>>(feats1,    W1, b1, hnei1, NN1);
    gemm64_kernel<DIN, true><<<cdiv(NN2, 64), 256>>>(feats2,    W2, b2, hnei2, NN2);
    gemm64_kernel<DIN, true><<<cdiv(NN,  64), 256>>>(feats0,    W0, b0, htar,  NN);
    gemm64_kernel<DIN, true><<<cdiv(NN,  64), 256>>>(mask_feat, W0, b0, hmask, NN);

    // Gather-aggregate (float4, half-warp per row, 8 rows in flight)
    agg_kernel<<<cdiv((long long)NN * 32, 256), 256>>>(row1, deg1, edst1,
                                                       (const float4*)hnei1, (float4*)sum1, NN);
    agg_kernel<<<cdiv((long long)NN * 32, 256), 256>>>(row2, deg2, edst2,
                                                       (const float4*)hnei2, (float4*)sum2, NN);

    // Fused A-GEMM x2 + epilogue (divide by deg inside)
    gemm_epi_kernel<<<cdiv(NN, 64), 256>>>(sum1, A0, sum2, A1, deg1, deg2,
                                           (const float4*)hmask, out);
}

// round 10
// speedup vs baseline: 1.0661x; 1.0661x over previous
#include <cuda_runtime.h>
#include <math.h>

// Problem constants (fixed by the reference)
constexpr int NN  = 100000;
constexpr int NN1 = 60000;
constexpr int NN2 = 30000;
constexpr int EE  = 1600000;
constexpr int DIN = 128;
constexpr int HH  = 64;

// ---------------- float scratch ----------------
constexpr long long F_HMASK = 0;
constexpr long long F_HNEI1 = F_HMASK + (long long)NN * HH;
constexpr long long F_HNEI2 = F_HNEI1 + (long long)NN1 * HH;
constexpr long long F_SUM1  = F_HNEI2 + (long long)NN2 * HH;
constexpr long long F_SUM2  = F_SUM1 + (long long)NN * HH;
constexpr long long F_TOTAL = F_SUM2 + (long long)NN * HH;

__device__ float g_fscratch[F_TOTAL];

// ---------------- int scratch ----------------
constexpr long long I_DEG1 = 0;
constexpr long long I_DEG2 = I_DEG1 + NN;
constexpr long long I_ROW1 = I_DEG2 + NN;
constexpr long long I_ROW2 = I_ROW1 + NN;
constexpr long long I_CUR1 = I_ROW2 + NN;
constexpr long long I_CUR2 = I_CUR1 + NN;
constexpr long long I_CTR  = I_CUR2 + NN;     // 2 counters, padded
constexpr long long I_EDST1 = I_CTR + 32;
constexpr long long I_EDST2 = I_EDST1 + EE;
constexpr long long I_TOTAL = I_EDST2 + EE;

__device__ int g_iscratch[I_TOTAL];

// ---------------- helpers ----------------
__device__ __forceinline__ float elu1(float x) { return x > 0.f ? x : expm1f(x); }
__device__ __forceinline__ float4 elu4(float4 v) {
    v.x = elu1(v.x); v.y = elu1(v.y); v.z = elu1(v.z); v.w = elu1(v.w);
    return v;
}

// ================= input GEMM: Y = elu(X[r,:128] @ W[:,64] + b) =================
// 64x64 tile, 128 threads, 8x4 register block per thread. 64KB static smem
// (same footprint as the proven R8 kernel). Per k4 iteration each thread does
// 12 LDS.128 -> 128 FFMA (vs 8 -> 64 before): 33% less LDS pressure on the
// measured L1-bound pipe.
__global__ __launch_bounds__(128)
void gemm64_kernel(const float* __restrict__ X, const float* __restrict__ W,
                   const float* __restrict__ b, float* __restrict__ Y, int rows)
{
    constexpr int K4 = DIN / 4;          // 32
    __shared__ float4 Xs[64 * K4];       // 32KB
    __shared__ float4 Wt[64 * K4];       // 32KB

    const int t = threadIdx.x;
    const int rowBase = blockIdx.x * 64;

    const float4* X4 = (const float4*)X;
#pragma unroll
    for (int it = 0; it < 16; it++) {
        int idx = t + it * 128;          // [0, 2048)
        int r  = idx >> 5;
        int k4 = idx & 31;
        int gr = rowBase + r;
        float4 v = make_float4(0.f, 0.f, 0.f, 0.f);
        if (gr < rows) v = X4[(long long)gr * K4 + k4];
        Xs[idx] = v;
    }
#pragma unroll
    for (int it = 0; it < 64; it++) {
        int idx = t + it * 128;          // [0, 8192)
        int k = idx >> 6;
        int c = idx & 63;
        ((float*)&Wt[c * K4 + ((k >> 2) ^ ((c >> 2) & 7))])[k & 3] = W[idx];
    }
    __syncthreads();

    const int c4  = t & 15;              // float4 column group
    const int r0  = (t >> 4) * 8;        // 8 rows per thread
    const int swz = c4 & 7;

    float acc[8][4];
#pragma unroll
    for (int i = 0; i < 8; i++)
#pragma unroll
        for (int j = 0; j < 4; j++) acc[i][j] = 0.f;

#pragma unroll 4
    for (int k4 = 0; k4 < K4; k4++) {
        float4 xv[8];
#pragma unroll
        for (int i = 0; i < 8; i++) xv[i] = Xs[(r0 + i) * K4 + k4];
#pragma unroll
        for (int j = 0; j < 4; j++) {
            float4 wv = Wt[(c4 * 4 + j) * K4 + (k4 ^ swz)];
#pragma unroll
            for (int i = 0; i < 8; i++)
                acc[i][j] += xv[i].x * wv.x + xv[i].y * wv.y +
                             xv[i].z * wv.z + xv[i].w * wv.w;
        }
    }

    float4 bias = ((const float4*)b)[c4];
    float4* Y4 = (float4*)Y;
#pragma unroll
    for (int i = 0; i < 8; i++) {
        int gr = rowBase + r0 + i;
        if (gr < rows) {
            float4 o = make_float4(acc[i][0] + bias.x, acc[i][1] + bias.y,
                                   acc[i][2] + bias.z, acc[i][3] + bias.w);
            Y4[(long long)gr * 16 + c4] = elu4(o);
        }
    }
}

// ================= CSR build (proven R8 versions) =================
__global__ __launch_bounds__(256)
void zero_kernel(int* __restrict__ d1, int* __restrict__ d2, int* __restrict__ ctr)
{
    int i = blockIdx.x * 256 + threadIdx.x;
    if (i < NN) { d1[i] = 0; d2[i] = 0; }
    if (i < 2) ctr[i] = 0;
}

__global__ __launch_bounds__(256)
void hist2_kernel(const int* __restrict__ src1, const int* __restrict__ src2,
                  int* __restrict__ deg1, int* __restrict__ deg2)
{
    int e = blockIdx.x * 256 + threadIdx.x;
    if (e < EE)            atomicAdd(deg1 + __ldg(src1 + e), 1);
    else if (e < 2 * EE)   atomicAdd(deg2 + __ldg(src2 + e - EE), 1);
}

__global__ __launch_bounds__(256)
void base2_kernel(const int* __restrict__ deg1, int* __restrict__ row1, int* __restrict__ cur1,
                  const int* __restrict__ deg2, int* __restrict__ row2, int* __restrict__ cur2,
                  int* __restrict__ ctr, int nb)
{
    __shared__ int warpTot[8];
    __shared__ int blockBase;
    int rel = blockIdx.x >= nb;
    const int* deg = rel ? deg2 : deg1;
    int* rowp = rel ? row2 : row1;
    int* cur  = rel ? cur2 : cur1;
    int* counter = ctr + rel;

    int i = (blockIdx.x - rel * nb) * 256 + threadIdx.x;
    int lane = threadIdx.x & 31;
    int wid  = threadIdx.x >> 5;

    int d = (i < NN) ? deg[i] : 0;
    int x = d;
#pragma unroll
    for (int o = 1; o < 32; o <<= 1) {
        int y = __shfl_up_sync(0xffffffffu, x, o);
        if (lane >= o) x += y;
    }
    if (lane == 31) warpTot[wid] = x;
    __syncthreads();
    if (threadIdx.x == 0) {
        int s = 0;
#pragma unroll
        for (int w = 0; w < 8; w++) { int tw = warpTot[w]; warpTot[w] = s; s += tw; }
        blockBase = atomicAdd(counter, s);
    }
    __syncthreads();
    int base = blockBase + warpTot[wid] + x - d;
    if (i < NN) { rowp[i] = base; cur[i] = base; }
}

__global__ __launch_bounds__(256)
void reorder2_kernel(const int* __restrict__ src1, const int* __restrict__ dst1,
                     int* __restrict__ cur1, int* __restrict__ edst1,
                     const int* __restrict__ src2, const int* __restrict__ dst2,
                     int* __restrict__ cur2, int* __restrict__ edst2)
{
    int e = blockIdx.x * 256 + threadIdx.x;
    if (e < EE) {
        int s = __ldg(src1 + e);
        int pos = atomicAdd(cur1 + s, 1);
        edst1[pos] = __ldg(dst1 + e);
    } else if (e < 2 * EE) {
        e -= EE;
        int s = __ldg(src2 + e);
        int pos = atomicAdd(cur2 + s, 1);
        edst2[pos] = __ldg(dst2 + e);
    }
}

// ================= aggregate: one warp per node (proven R8 float2 version) =========
__global__ __launch_bounds__(256)
void agg_kernel(const int* __restrict__ rowptr, const int* __restrict__ deg,
                const int* __restrict__ edst, const float2* __restrict__ hnei,
                float2* __restrict__ sum, int n)
{
    int warp = (blockIdx.x * 256 + threadIdx.x) >> 5;
    int lane = threadIdx.x & 31;
    if (warp >= n) return;

    int base = __ldg(rowptr + warp);
    int d    = __ldg(deg + warp);

    float2 acc = make_float2(0.f, 0.f);
    for (int j0 = 0; j0 < d; j0 += 32) {
        int e = 0;
        if (j0 + lane < d) e = __ldg(edst + base + j0 + lane);
        int m = min(32, d - j0);
        int jj = 0;
        for (; jj + 4 <= m; jj += 4) {
            int d0 = __shfl_sync(0xffffffffu, e, jj);
            int d1 = __shfl_sync(0xffffffffu, e, jj + 1);
            int d2 = __shfl_sync(0xffffffffu, e, jj + 2);
            int d3 = __shfl_sync(0xffffffffu, e, jj + 3);
            float2 v0 = __ldg(hnei + (long long)d0 * 32 + lane);
            float2 v1 = __ldg(hnei + (long long)d1 * 32 + lane);
            float2 v2 = __ldg(hnei + (long long)d2 * 32 + lane);
            float2 v3 = __ldg(hnei + (long long)d3 * 32 + lane);
            acc.x += v0.x + v1.x + v2.x + v3.x;
            acc.y += v0.y + v1.y + v2.y + v3.y;
        }
        for (; jj < m; jj++) {
            int dd = __shfl_sync(0xffffffffu, e, jj);
            float2 v = __ldg(hnei + (long long)dd * 32 + lane);
            acc.x += v.x;
            acc.y += v.y;
        }
    }
    sum[(long long)warp * 32 + lane] = acc;
}

// ================= fused A-GEMM x2 + epilogue (32KB static smem) =================
__global__ __launch_bounds__(256)
void gemm_epi_kernel(const float* __restrict__ sum1, const float* __restrict__ A0,
                     const float* __restrict__ sum2, const float* __restrict__ A1,
                     const int* __restrict__ deg1, const int* __restrict__ deg2,
                     const float4* __restrict__ hmask, float* __restrict__ out)
{
    constexpr int K4 = HH / 4;           // 16
    __shared__ float4 Xs[64 * K4];       // 16KB
    __shared__ float4 Wt[64 * K4];       // 16KB

    const int t = threadIdx.x;
    const int rowBase = blockIdx.x * 64;
    const int c4  = t & 15;
    const int r0  = (t >> 4) * 4;
    const int swz = c4 & 7;

    float acc1[4][4], acc2[4][4];

    for (int phase = 0; phase < 2; phase++) {
        const float4* X4 = phase ? (const float4*)sum2 : (const float4*)sum1;
        const float* W   = phase ? A1 : A0;
        if (phase) __syncthreads();      // all reads of phase-0 tiles done

#pragma unroll
        for (int it = 0; it < 4; it++) {
            int idx = t + it * 256;      // [0, 1024)
            int r  = idx >> 4;
            int k4 = idx & 15;
            int gr = rowBase + r;
            float4 v = make_float4(0.f, 0.f, 0.f, 0.f);
            if (gr < NN) v = X4[(long long)gr * K4 + k4];
            Xs[idx] = v;
        }
#pragma unroll
        for (int it = 0; it < 16; it++) {
            int idx = t + it * 256;      // [0, 4096)
            int k = idx >> 6;
            int c = idx & 63;
            ((float*)&Wt[c * K4 + ((k >> 2) ^ ((c >> 2) & 7))])[k & 3] = W[idx];
        }
        __syncthreads();

        float (*acc)[4] = phase ? acc2 : acc1;
#pragma unroll
        for (int i = 0; i < 4; i++)
#pragma unroll
            for (int j = 0; j < 4; j++) acc[i][j] = 0.f;

#pragma unroll 4
        for (int k4 = 0; k4 < K4; k4++) {
            float4 xv[4];
#pragma unroll
            for (int i = 0; i < 4; i++) xv[i] = Xs[(r0 + i) * K4 + k4];
#pragma unroll
            for (int j = 0; j < 4; j++) {
                float4 wv = Wt[(c4 * 4 + j) * K4 + (k4 ^ swz)];
#pragma unroll
                for (int i = 0; i < 4; i++)
                    acc[i][j] += xv[i].x * wv.x + xv[i].y * wv.y +
                                 xv[i].z * wv.z + xv[i].w * wv.w;
            }
        }
    }

    // epilogue
    float4* O = (float4*)out;
    const float4* HT = O + 4LL * NN * 16;
#pragma unroll
    for (int i = 0; i < 4; i++) {
        int gr = rowBase + r0 + i;
        if (gr >= NN) continue;
        int d1 = __ldg(deg1 + gr);
        int d2 = __ldg(deg2 + gr);
        float inv1 = d1 > 0 ? 1.f / (float)d1 : 1.f;
        float inv2 = d2 > 0 ? 1.f / (float)d2 : 1.f;
        float4 a1 = make_float4(acc1[i][0] * inv1, acc1[i][1] * inv1,
                                acc1[i][2] * inv1, acc1[i][3] * inv1);
        float4 a2 = make_float4(acc2[i][0] * inv2, acc2[i][1] * inv2,
                                acc2[i][2] * inv2, acc2[i][3] * inv2);
        long long g = (long long)gr * 16 + c4;
        float4 ht = HT[g];
        float4 hm = hmask[g];
        float4 v;
        v = make_float4(ht.x + a1.x, ht.y + a1.y, ht.z + a1.z, ht.w + a1.w);
        O[0LL * NN * 16 + g] = elu4(v);
        v = make_float4(hm.x + a1.x, hm.y + a1.y, hm.z + a1.z, hm.w + a1.w);
        O[1LL * NN * 16 + g] = elu4(v);
        v = make_float4(ht.x + a2.x, ht.y + a2.y, ht.z + a2.z, ht.w + a2.w);
        O[2LL * NN * 16 + g] = elu4(v);
        v = make_float4(hm.x + a2.x, hm.y + a2.y, hm.z + a2.z, hm.w + a2.w);
        O[3LL * NN * 16 + g] = elu4(v);
    }
}

// ================= launch (single stream, no statics, no attribute calls) =========
extern "C" void kernel_launch(void* const* d_in, const int* in_sizes, int n_in,
                              void* d_out, int out_size)
{
    const float* feats0    = (const float*)d_in[0];
    const float* feats1    = (const float*)d_in[1];
    const float* feats2    = (const float*)d_in[2];
    const float* mask_feat = (const float*)d_in[3];
    const int*   src1      = (const int*)d_in[4];
    const int*   dst1      = (const int*)d_in[5];
    const int*   src2      = (const int*)d_in[6];
    const int*   dst2      = (const int*)d_in[7];
    const float* W0        = (const float*)d_in[8];
    const float* b0        = (const float*)d_in[9];
    const float* W1        = (const float*)d_in[10];
    const float* b1        = (const float*)d_in[11];
    const float* W2        = (const float*)d_in[12];
    const float* b2        = (const float*)d_in[13];
    const float* A0        = (const float*)d_in[14];
    const float* A1        = (const float*)d_in[15];

    float* out = (float*)d_out;

    void* fp = nullptr; cudaGetSymbolAddress(&fp, g_fscratch);
    void* ip = nullptr; cudaGetSymbolAddress(&ip, g_iscratch);
    float* F = (float*)fp;
    int*   I = (int*)ip;

    float* hmask = F + F_HMASK;
    float* hnei1 = F + F_HNEI1;
    float* hnei2 = F + F_HNEI2;
    float* sum1  = F + F_SUM1;
    float* sum2  = F + F_SUM2;

    int* deg1 = I + I_DEG1;
    int* deg2 = I + I_DEG2;
    int* row1 = I + I_ROW1;
    int* row2 = I + I_ROW2;
    int* cur1 = I + I_CUR1;
    int* cur2 = I + I_CUR2;
    int* ctr  = I + I_CTR;
    int* edst1 = I + I_EDST1;
    int* edst2 = I + I_EDST2;

    float* htar = out + 4LL * NN * HH;

    auto cdiv = [](long long a, long long b) { return (int)((a + b - 1) / b); };

    const int NB = cdiv(NN, 256);

    // CSR build chain
    zero_kernel<<<NB, 256>>>(deg1, deg2, ctr);
    hist2_kernel<<<cdiv(2LL * EE, 256), 256>>>(src1, src2, deg1, deg2);
    base2_kernel<<<2 * NB, 256>>>(deg1, row1, cur1, deg2, row2, cur2, ctr, NB);
    reorder2_kernel<<<cdiv(2LL * EE, 256), 256>>>(src1, dst1, cur1, edst1,
                                                  src2, dst2, cur2, edst2);

    // Input GEMMs (+bias +ELU) — 128 threads, 8x4 blocking
    gemm64_kernel<<<cdiv(NN1, 64), 128>>>(feats1,    W1, b1, hnei1, NN1);
    gemm64_kernel<<<cdiv(NN2, 64), 128>>>(feats2,    W2, b2, hnei2, NN2);
    gemm64_kernel<<<cdiv(NN,  64), 128>>>(feats0,    W0, b0, htar,  NN);
    gemm64_kernel<<<cdiv(NN,  64), 128>>>(mask_feat, W0, b0, hmask, NN);

    // Gather-aggregate (proven float2, one warp per node)
    agg_kernel<<<cdiv((long long)NN * 32, 256), 256>>>(row1, deg1, edst1,
                                                       (const float2*)hnei1, (float2*)sum1, NN);
    agg_kernel<<<cdiv((long long)NN * 32, 256), 256>>>(row2, deg2, edst2,
                                                       (const float2*)hnei2, (float2*)sum2, NN);

    // Fused A-GEMM x2 + epilogue (divide by deg inside)
    gemm_epi_kernel<<<cdiv(NN, 64), 256>>>(sum1, A0, sum2, A1, deg1, deg2,
                                           (const float4*)hmask, out);
}

// round 13
// speedup vs baseline: 1.0802x; 1.0132x over previous
#include <cuda_runtime.h>
#include <math.h>

// Problem constants (fixed by the reference)
constexpr int NN  = 100000;
constexpr int NN1 = 60000;
constexpr int NN2 = 30000;
constexpr int EE  = 1600000;
constexpr int DIN = 128;
constexpr int HH  = 64;

// ---------------- float scratch ----------------
constexpr long long F_HMASK = 0;
constexpr long long F_HNEI1 = F_HMASK + (long long)NN * HH;
constexpr long long F_HNEI2 = F_HNEI1 + (long long)NN1 * HH;
constexpr long long F_SUM1  = F_HNEI2 + (long long)NN2 * HH;
constexpr long long F_SUM2  = F_SUM1 + (long long)NN * HH;
constexpr long long F_TOTAL = F_SUM2 + (long long)NN * HH;

__device__ float g_fscratch[F_TOTAL];

// ---------------- int scratch ----------------
constexpr long long I_DEG1 = 0;
constexpr long long I_DEG2 = I_DEG1 + NN;
constexpr long long I_ROW1 = I_DEG2 + NN;
constexpr long long I_ROW2 = I_ROW1 + NN;
constexpr long long I_CUR1 = I_ROW2 + NN;
constexpr long long I_CUR2 = I_CUR1 + NN;
constexpr long long I_CTR  = I_CUR2 + NN;     // 2 counters, padded
constexpr long long I_EDST1 = I_CTR + 32;
constexpr long long I_EDST2 = I_EDST1 + EE;
constexpr long long I_TOTAL = I_EDST2 + EE;

__device__ int g_iscratch[I_TOTAL];

// ---------------- helpers ----------------
__device__ __forceinline__ float elu1(float x) { return x > 0.f ? x : expm1f(x); }
__device__ __forceinline__ float4 elu4(float4 v) {
    v.x = elu1(v.x); v.y = elu1(v.y); v.z = elu1(v.z); v.w = elu1(v.w);
    return v;
}

// ================= input GEMM: Y = elu(X[r,:128] @ W[:,64] + b) =================
// 64x64 tile, 128 threads, 8x4 register block per thread. 64KB static smem.
__global__ __launch_bounds__(128)
void gemm64_kernel(const float* __restrict__ X, const float* __restrict__ W,
                   const float* __restrict__ b, float* __restrict__ Y, int rows)
{
    constexpr int K4 = DIN / 4;          // 32
    __shared__ float4 Xs[64 * K4];       // 32KB
    __shared__ float4 Wt[64 * K4];       // 32KB

    const int t = threadIdx.x;
    const int rowBase = blockIdx.x * 64;

    const float4* X4 = (const float4*)X;
#pragma unroll
    for (int it = 0; it < 16; it++) {
        int idx = t + it * 128;          // [0, 2048)
        int r  = idx >> 5;
        int k4 = idx & 31;
        int gr = rowBase + r;
        float4 v = make_float4(0.f, 0.f, 0.f, 0.f);
        if (gr < rows) v = X4[(long long)gr * K4 + k4];
        Xs[idx] = v;
    }
#pragma unroll
    for (int it = 0; it < 64; it++) {
        int idx = t + it * 128;          // [0, 8192)
        int k = idx >> 6;
        int c = idx & 63;
        ((float*)&Wt[c * K4 + ((k >> 2) ^ ((c >> 2) & 7))])[k & 3] = W[idx];
    }
    __syncthreads();

    const int c4  = t & 15;              // float4 column group
    const int r0  = (t >> 4) * 8;        // 8 rows per thread
    const int swz = c4 & 7;

    float acc[8][4];
#pragma unroll
    for (int i = 0; i < 8; i++)
#pragma unroll
        for (int j = 0; j < 4; j++) acc[i][j] = 0.f;

#pragma unroll 4
    for (int k4 = 0; k4 < K4; k4++) {
        float4 xv[8];
#pragma unroll
        for (int i = 0; i < 8; i++) xv[i] = Xs[(r0 + i) * K4 + k4];
#pragma unroll
        for (int j = 0; j < 4; j++) {
            float4 wv = Wt[(c4 * 4 + j) * K4 + (k4 ^ swz)];
#pragma unroll
            for (int i = 0; i < 8; i++)
                acc[i][j] += xv[i].x * wv.x + xv[i].y * wv.y +
                             xv[i].z * wv.z + xv[i].w * wv.w;
        }
    }

    float4 bias = ((const float4*)b)[c4];
    float4* Y4 = (float4*)Y;
#pragma unroll
    for (int i = 0; i < 8; i++) {
        int gr = rowBase + r0 + i;
        if (gr < rows) {
            float4 o = make_float4(acc[i][0] + bias.x, acc[i][1] + bias.y,
                                   acc[i][2] + bias.z, acc[i][3] + bias.w);
            Y4[(long long)gr * 16 + c4] = elu4(o);
        }
    }
}

// ================= CSR build (proven versions) =================
__global__ __launch_bounds__(256)
void zero_kernel(int* __restrict__ d1, int* __restrict__ d2, int* __restrict__ ctr)
{
    int i = blockIdx.x * 256 + threadIdx.x;
    if (i < NN) { d1[i] = 0; d2[i] = 0; }
    if (i < 2) ctr[i] = 0;
}

__global__ __launch_bounds__(256)
void hist2_kernel(const int* __restrict__ src1, const int* __restrict__ src2,
                  int* __restrict__ deg1, int* __restrict__ deg2)
{
    int e = blockIdx.x * 256 + threadIdx.x;
    if (e < EE)            atomicAdd(deg1 + __ldg(src1 + e), 1);
    else if (e < 2 * EE)   atomicAdd(deg2 + __ldg(src2 + e - EE), 1);
}

__global__ __launch_bounds__(256)
void base2_kernel(const int* __restrict__ deg1, int* __restrict__ row1, int* __restrict__ cur1,
                  const int* __restrict__ deg2, int* __restrict__ row2, int* __restrict__ cur2,
                  int* __restrict__ ctr, int nb)
{
    __shared__ int warpTot[8];
    __shared__ int blockBase;
    int rel = blockIdx.x >= nb;
    const int* deg = rel ? deg2 : deg1;
    int* rowp = rel ? row2 : row1;
    int* cur  = rel ? cur2 : cur1;
    int* counter = ctr + rel;

    int i = (blockIdx.x - rel * nb) * 256 + threadIdx.x;
    int lane = threadIdx.x & 31;
    int wid  = threadIdx.x >> 5;

    int d = (i < NN) ? deg[i] : 0;
    int x = d;
#pragma unroll
    for (int o = 1; o < 32; o <<= 1) {
        int y = __shfl_up_sync(0xffffffffu, x, o);
        if (lane >= o) x += y;
    }
    if (lane == 31) warpTot[wid] = x;
    __syncthreads();
    if (threadIdx.x == 0) {
        int s = 0;
#pragma unroll
        for (int w = 0; w < 8; w++) { int tw = warpTot[w]; warpTot[w] = s; s += tw; }
        blockBase = atomicAdd(counter, s);
    }
    __syncthreads();
    int base = blockBase + warpTot[wid] + x - d;
    if (i < NN) { rowp[i] = base; cur[i] = base; }
}

__global__ __launch_bounds__(256)
void reorder2_kernel(const int* __restrict__ src1, const int* __restrict__ dst1,
                     int* __restrict__ cur1, int* __restrict__ edst1,
                     const int* __restrict__ src2, const int* __restrict__ dst2,
                     int* __restrict__ cur2, int* __restrict__ edst2)
{
    int e = blockIdx.x * 256 + threadIdx.x;
    if (e < EE) {
        int s = __ldg(src1 + e);
        int pos = atomicAdd(cur1 + s, 1);
        edst1[pos] = __ldg(dst1 + e);
    } else if (e < 2 * EE) {
        e -= EE;
        int s = __ldg(src2 + e);
        int pos = atomicAdd(cur2 + s, 1);
        edst2[pos] = __ldg(dst2 + e);
    }
}

// ================= aggregate: one warp per node, 8 row-gathers in flight =========
__global__ __launch_bounds__(256)
void agg_kernel(const int* __restrict__ rowptr, const int* __restrict__ deg,
                const int* __restrict__ edst, const float2* __restrict__ hnei,
                float2* __restrict__ sum, int n)
{
    int warp = (blockIdx.x * 256 + threadIdx.x) >> 5;
    int lane = threadIdx.x & 31;
    if (warp >= n) return;

    int base = __ldg(rowptr + warp);
    int d    = __ldg(deg + warp);

    float2 acc = make_float2(0.f, 0.f);
    for (int j0 = 0; j0 < d; j0 += 32) {
        int e = 0;
        if (j0 + lane < d) e = __ldg(edst + base + j0 + lane);
        int m = min(32, d - j0);
        int jj = 0;
        // 8 independent row-gathers in flight (MLP=8 vs L2 latency ~250cyc)
        for (; jj + 8 <= m; jj += 8) {
            int i0 = __shfl_sync(0xffffffffu, e, jj);
            int i1 = __shfl_sync(0xffffffffu, e, jj + 1);
            int i2 = __shfl_sync(0xffffffffu, e, jj + 2);
            int i3 = __shfl_sync(0xffffffffu, e, jj + 3);
            int i4 = __shfl_sync(0xffffffffu, e, jj + 4);
            int i5 = __shfl_sync(0xffffffffu, e, jj + 5);
            int i6 = __shfl_sync(0xffffffffu, e, jj + 6);
            int i7 = __shfl_sync(0xffffffffu, e, jj + 7);
            float2 v0 = __ldg(hnei + (long long)i0 * 32 + lane);
            float2 v1 = __ldg(hnei + (long long)i1 * 32 + lane);
            float2 v2 = __ldg(hnei + (long long)i2 * 32 + lane);
            float2 v3 = __ldg(hnei + (long long)i3 * 32 + lane);
            float2 v4 = __ldg(hnei + (long long)i4 * 32 + lane);
            float2 v5 = __ldg(hnei + (long long)i5 * 32 + lane);
            float2 v6 = __ldg(hnei + (long long)i6 * 32 + lane);
            float2 v7 = __ldg(hnei + (long long)i7 * 32 + lane);
            acc.x += (v0.x + v1.x) + (v2.x + v3.x) + (v4.x + v5.x) + (v6.x + v7.x);
            acc.y += (v0.y + v1.y) + (v2.y + v3.y) + (v4.y + v5.y) + (v6.y + v7.y);
        }
        for (; jj + 4 <= m; jj += 4) {
            int i0 = __shfl_sync(0xffffffffu, e, jj);
            int i1 = __shfl_sync(0xffffffffu, e, jj + 1);
            int i2 = __shfl_sync(0xffffffffu, e, jj + 2);
            int i3 = __shfl_sync(0xffffffffu, e, jj + 3);
            float2 v0 = __ldg(hnei + (long long)i0 * 32 + lane);
            float2 v1 = __ldg(hnei + (long long)i1 * 32 + lane);
            float2 v2 = __ldg(hnei + (long long)i2 * 32 + lane);
            float2 v3 = __ldg(hnei + (long long)i3 * 32 + lane);
            acc.x += (v0.x + v1.x) + (v2.x + v3.x);
            acc.y += (v0.y + v1.y) + (v2.y + v3.y);
        }
        for (; jj < m; jj++) {
            int dd = __shfl_sync(0xffffffffu, e, jj);
            float2 v = __ldg(hnei + (long long)dd * 32 + lane);
            acc.x += v.x;
            acc.y += v.y;
        }
    }
    sum[(long long)warp * 32 + lane] = acc;
}

// ================= fused A-GEMM x2 + epilogue (32KB static smem) =================
__global__ __launch_bounds__(256)
void gemm_epi_kernel(const float* __restrict__ sum1, const float* __restrict__ A0,
                     const float* __restrict__ sum2, const float* __restrict__ A1,
                     const int* __restrict__ deg1, const int* __restrict__ deg2,
                     const float4* __restrict__ hmask, float* __restrict__ out)
{
    constexpr int K4 = HH / 4;           // 16
    __shared__ float4 Xs[64 * K4];       // 16KB
    __shared__ float4 Wt[64 * K4];       // 16KB

    const int t = threadIdx.x;
    const int rowBase = blockIdx.x * 64;
    const int c4  = t & 15;
    const int r0  = (t >> 4) * 4;
    const int swz = c4 & 7;

    float acc1[4][4], acc2[4][4];

    for (int phase = 0; phase < 2; phase++) {
        const float4* X4 = phase ? (const float4*)sum2 : (const float4*)sum1;
        const float* W   = phase ? A1 : A0;
        if (phase) __syncthreads();      // all reads of phase-0 tiles done

#pragma unroll
        for (int it = 0; it < 4; it++) {
            int idx = t + it * 256;      // [0, 1024)
            int r  = idx >> 4;
            int k4 = idx & 15;
            int gr = rowBase + r;
            float4 v = make_float4(0.f, 0.f, 0.f, 0.f);
            if (gr < NN) v = X4[(long long)gr * K4 + k4];
            Xs[idx] = v;
        }
#pragma unroll
        for (int it = 0; it < 16; it++) {
            int idx = t + it * 256;      // [0, 4096)
            int k = idx >> 6;
            int c = idx & 63;
            ((float*)&Wt[c * K4 + ((k >> 2) ^ ((c >> 2) & 7))])[k & 3] = W[idx];
        }
        __syncthreads();

        float (*acc)[4] = phase ? acc2 : acc1;
#pragma unroll
        for (int i = 0; i < 4; i++)
#pragma unroll
            for (int j = 0; j < 4; j++) acc[i][j] = 0.f;

#pragma unroll 4
        for (int k4 = 0; k4 < K4; k4++) {
            float4 xv[4];
#pragma unroll
            for (int i = 0; i < 4; i++) xv[i] = Xs[(r0 + i) * K4 + k4];
#pragma unroll
            for (int j = 0; j < 4; j++) {
                float4 wv = Wt[(c4 * 4 + j) * K4 + (k4 ^ swz)];
#pragma unroll
                for (int i = 0; i < 4; i++)
                    acc[i][j] += xv[i].x * wv.x + xv[i].y * wv.y +
                                 xv[i].z * wv.z + xv[i].w * wv.w;
            }
        }
    }

    // epilogue
    float4* O = (float4*)out;
    const float4* HT = O + 4LL * NN * 16;
#pragma unroll
    for (int i = 0; i < 4; i++) {
        int gr = rowBase + r0 + i;
        if (gr >= NN) continue;
        int d1 = __ldg(deg1 + gr);
        int d2 = __ldg(deg2 + gr);
        float inv1 = d1 > 0 ? 1.f / (float)d1 : 1.f;
        float inv2 = d2 > 0 ? 1.f / (float)d2 : 1.f;
        float4 a1 = make_float4(acc1[i][0] * inv1, acc1[i][1] * inv1,
                                acc1[i][2] * inv1, acc1[i][3] * inv1);
        float4 a2 = make_float4(acc2[i][0] * inv2, acc2[i][1] * inv2,
                                acc2[i][2] * inv2, acc2[i][3] * inv2);
        long long g = (long long)gr * 16 + c4;
        float4 ht = HT[g];
        float4 hm = hmask[g];
        float4 v;
        v = make_float4(ht.x + a1.x, ht.y + a1.y, ht.z + a1.z, ht.w + a1.w);
        O[0LL * NN * 16 + g] = elu4(v);
        v = make_float4(hm.x + a1.x, hm.y + a1.y, hm.z + a1.z, hm.w + a1.w);
        O[1LL * NN * 16 + g] = elu4(v);
        v = make_float4(ht.x + a2.x, ht.y + a2.y, ht.z + a2.z, ht.w + a2.w);
        O[2LL * NN * 16 + g] = elu4(v);
        v = make_float4(hm.x + a2.x, hm.y + a2.y, hm.z + a2.z, hm.w + a2.w);
        O[3LL * NN * 16 + g] = elu4(v);
    }
}

// ================= launch (single stream, no statics, no attribute calls) =========
extern "C" void kernel_launch(void* const* d_in, const int* in_sizes, int n_in,
                              void* d_out, int out_size)
{
    const float* feats0    = (const float*)d_in[0];
    const float* feats1    = (const float*)d_in[1];
    const float* feats2    = (const float*)d_in[2];
    const float* mask_feat = (const float*)d_in[3];
    const int*   src1      = (const int*)d_in[4];
    const int*   dst1      = (const int*)d_in[5];
    const int*   src2      = (const int*)d_in[6];
    const int*   dst2      = (const int*)d_in[7];
    const float* W0        = (const float*)d_in[8];
    const float* b0        = (const float*)d_in[9];
    const float* W1        = (const float*)d_in[10];
    const float* b1        = (const float*)d_in[11];
    const float* W2        = (const float*)d_in[12];
    const float* b2        = (const float*)d_in[13];
    const float* A0        = (const float*)d_in[14];
    const float* A1        = (const float*)d_in[15];

    float* out = (float*)d_out;

    void* fp = nullptr; cudaGetSymbolAddress(&fp, g_fscratch);
    void* ip = nullptr; cudaGetSymbolAddress(&ip, g_iscratch);
    float* F = (float*)fp;
    int*   I = (int*)ip;

    float* hmask = F + F_HMASK;
    float* hnei1 = F + F_HNEI1;
    float* hnei2 = F + F_HNEI2;
    float* sum1  = F + F_SUM1;
    float* sum2  = F + F_SUM2;

    int* deg1 = I + I_DEG1;
    int* deg2 = I + I_DEG2;
    int* row1 = I + I_ROW1;
    int* row2 = I + I_ROW2;
    int* cur1 = I + I_CUR1;
    int* cur2 = I + I_CUR2;
    int* ctr  = I + I_CTR;
    int* edst1 = I + I_EDST1;
    int* edst2 = I + I_EDST2;

    float* htar = out + 4LL * NN * HH;

    auto cdiv = [](long long a, long long b) { return (int)((a + b - 1) / b); };

    const int NB = cdiv(NN, 256);

    // CSR build chain
    zero_kernel<<<NB, 256>>>(deg1, deg2, ctr);
    hist2_kernel<<<cdiv(2LL * EE, 256), 256>>>(src1, src2, deg1, deg2);
    base2_kernel<<<2 * NB, 256>>>(deg1, row1, cur1, deg2, row2, cur2, ctr, NB);
    reorder2_kernel<<<cdiv(2LL * EE, 256), 256>>>(src1, dst1, cur1, edst1,
                                                  src2, dst2, cur2, edst2);

    // Input GEMMs (+bias +ELU) — 128 threads, 8x4 blocking
    gemm64_kernel<<<cdiv(NN1, 64), 128>>>(feats1,    W1, b1, hnei1, NN1);
    gemm64_kernel<<<cdiv(NN2, 64), 128>>>(feats2,    W2, b2, hnei2, NN2);
    gemm64_kernel<<<cdiv(NN,  64), 128>>>(feats0,    W0, b0, htar,  NN);
    gemm64_kernel<<<cdiv(NN,  64), 128>>>(mask_feat, W0, b0, hmask, NN);

    // Gather-aggregate (one warp per node, 8 gathers in flight)
    agg_kernel<<<cdiv((long long)NN * 32, 256), 256>>>(row1, deg1, edst1,
                                                       (const float2*)hnei1, (float2*)sum1, NN);
    agg_kernel<<<cdiv((long long)NN * 32, 256), 256>>>(row2, deg2, edst2,
                                                       (const float2*)hnei2, (float2*)sum2, NN);

    // Fused A-GEMM x2 + epilogue (divide by deg inside)
    gemm_epi_kernel<<<cdiv(NN, 64), 256>>>(sum1, A0, sum2, A1, deg1, deg2,
                                           (const float4*)hmask, out);
}

// round 15
// speedup vs baseline: 1.0831x; 1.0027x over previous
#include <cuda_runtime.h>
#include <cuda_fp16.h>
#include <math.h>

// Problem constants (fixed by the reference)
constexpr int NN  = 100000;
constexpr int NN1 = 60000;
constexpr int NN2 = 30000;
constexpr int EE  = 1600000;
constexpr int DIN = 128;
constexpr int HH  = 64;

// ---------------- float scratch ----------------
// hnei1/hnei2 are fp16 now; carve them from the float pool (2 halves = 1 float).
constexpr long long F_HMASK = 0;
constexpr long long F_HNEI1 = F_HMASK + (long long)NN * HH;          // NN1*HH halves = NN1*HH/2 floats
constexpr long long F_HNEI2 = F_HNEI1 + (long long)NN1 * HH / 2;
constexpr long long F_SUM1  = F_HNEI2 + (long long)NN2 * HH / 2;
constexpr long long F_SUM2  = F_SUM1 + (long long)NN * HH;
constexpr long long F_TOTAL = F_SUM2 + (long long)NN * HH;

__device__ float g_fscratch[F_TOTAL];

// ---------------- int scratch ----------------
constexpr long long I_DEG1 = 0;
constexpr long long I_DEG2 = I_DEG1 + NN;
constexpr long long I_ROW1 = I_DEG2 + NN;
constexpr long long I_ROW2 = I_ROW1 + NN;
constexpr long long I_CUR1 = I_ROW2 + NN;
constexpr long long I_CUR2 = I_CUR1 + NN;
constexpr long long I_CTR  = I_CUR2 + NN;     // 2 counters, padded
constexpr long long I_EDST1 = I_CTR + 32;
constexpr long long I_EDST2 = I_EDST1 + EE;
constexpr long long I_TOTAL = I_EDST2 + EE;

__device__ int g_iscratch[I_TOTAL];

// ---------------- helpers ----------------
__device__ __forceinline__ float elu1(float x) { return x > 0.f ? x : expm1f(x); }
__device__ __forceinline__ float4 elu4(float4 v) {
    v.x = elu1(v.x); v.y = elu1(v.y); v.z = elu1(v.z); v.w = elu1(v.w);
    return v;
}

// ================= input GEMM: Y = elu(X[r,:128] @ W[:,64] + b) =================
// 64x64 tile, 128 threads, 8x4 register block per thread. 64KB static smem.
// HALF_OUT: write fp16 rows (for the aggregation-only hnei buffers).
template<bool HALF_OUT>
__global__ __launch_bounds__(128)
void gemm64_kernel(const float* __restrict__ X, const float* __restrict__ W,
                   const float* __restrict__ b, void* __restrict__ Yv, int rows)
{
    constexpr int K4 = DIN / 4;          // 32
    __shared__ float4 Xs[64 * K4];       // 32KB
    __shared__ float4 Wt[64 * K4];       // 32KB

    const int t = threadIdx.x;
    const int rowBase = blockIdx.x * 64;

    const float4* X4 = (const float4*)X;
#pragma unroll
    for (int it = 0; it < 16; it++) {
        int idx = t + it * 128;          // [0, 2048)
        int r  = idx >> 5;
        int k4 = idx & 31;
        int gr = rowBase + r;
        float4 v = make_float4(0.f, 0.f, 0.f, 0.f);
        if (gr < rows) v = X4[(long long)gr * K4 + k4];
        Xs[idx] = v;
    }
#pragma unroll
    for (int it = 0; it < 64; it++) {
        int idx = t + it * 128;          // [0, 8192)
        int k = idx >> 6;
        int c = idx & 63;
        ((float*)&Wt[c * K4 + ((k >> 2) ^ ((c >> 2) & 7))])[k & 3] = W[idx];
    }
    __syncthreads();

    const int c4  = t & 15;              // float4 column group
    const int r0  = (t >> 4) * 8;        // 8 rows per thread
    const int swz = c4 & 7;

    float acc[8][4];
#pragma unroll
    for (int i = 0; i < 8; i++)
#pragma unroll
        for (int j = 0; j < 4; j++) acc[i][j] = 0.f;

#pragma unroll 4
    for (int k4 = 0; k4 < K4; k4++) {
        float4 xv[8];
#pragma unroll
        for (int i = 0; i < 8; i++) xv[i] = Xs[(r0 + i) * K4 + k4];
#pragma unroll
        for (int j = 0; j < 4; j++) {
            float4 wv = Wt[(c4 * 4 + j) * K4 + (k4 ^ swz)];
#pragma unroll
            for (int i = 0; i < 8; i++)
                acc[i][j] += xv[i].x * wv.x + xv[i].y * wv.y +
                             xv[i].z * wv.z + xv[i].w * wv.w;
        }
    }

    float4 bias = ((const float4*)b)[c4];
#pragma unroll
    for (int i = 0; i < 8; i++) {
        int gr = rowBase + r0 + i;
        if (gr < rows) {
            float4 o = make_float4(acc[i][0] + bias.x, acc[i][1] + bias.y,
                                   acc[i][2] + bias.z, acc[i][3] + bias.w);
            o = elu4(o);
            if (HALF_OUT) {
                __half2 h0 = __floats2half2_rn(o.x, o.y);
                __half2 h1 = __floats2half2_rn(o.z, o.w);
                uint2 pk;
                pk.x = *(unsigned*)&h0;
                pk.y = *(unsigned*)&h1;
                ((uint2*)Yv)[(long long)gr * 16 + c4] = pk;   // 8B = 4 halves
            } else {
                ((float4*)Yv)[(long long)gr * 16 + c4] = o;
            }
        }
    }
}

// ================= CSR build (proven versions) =================
__global__ __launch_bounds__(256)
void zero_kernel(int* __restrict__ d1, int* __restrict__ d2, int* __restrict__ ctr)
{
    int i = blockIdx.x * 256 + threadIdx.x;
    if (i < NN) { d1[i] = 0; d2[i] = 0; }
    if (i < 2) ctr[i] = 0;
}

__global__ __launch_bounds__(256)
void hist2_kernel(const int* __restrict__ src1, const int* __restrict__ src2,
                  int* __restrict__ deg1, int* __restrict__ deg2)
{
    int e = blockIdx.x * 256 + threadIdx.x;
    if (e < EE)            atomicAdd(deg1 + __ldg(src1 + e), 1);
    else if (e < 2 * EE)   atomicAdd(deg2 + __ldg(src2 + e - EE), 1);
}

__global__ __launch_bounds__(256)
void base2_kernel(const int* __restrict__ deg1, int* __restrict__ row1, int* __restrict__ cur1,
                  const int* __restrict__ deg2, int* __restrict__ row2, int* __restrict__ cur2,
                  int* __restrict__ ctr, int nb)
{
    __shared__ int warpTot[8];
    __shared__ int blockBase;
    int rel = blockIdx.x >= nb;
    const int* deg = rel ? deg2 : deg1;
    int* rowp = rel ? row2 : row1;
    int* cur  = rel ? cur2 : cur1;
    int* counter = ctr + rel;

    int i = (blockIdx.x - rel * nb) * 256 + threadIdx.x;
    int lane = threadIdx.x & 31;
    int wid  = threadIdx.x >> 5;

    int d = (i < NN) ? deg[i] : 0;
    int x = d;
#pragma unroll
    for (int o = 1; o < 32; o <<= 1) {
        int y = __shfl_up_sync(0xffffffffu, x, o);
        if (lane >= o) x += y;
    }
    if (lane == 31) warpTot[wid] = x;
    __syncthreads();
    if (threadIdx.x == 0) {
        int s = 0;
#pragma unroll
        for (int w = 0; w < 8; w++) { int tw = warpTot[w]; warpTot[w] = s; s += tw; }
        blockBase = atomicAdd(counter, s);
    }
    __syncthreads();
    int base = blockBase + warpTot[wid] + x - d;
    if (i < NN) { rowp[i] = base; cur[i] = base; }
}

__global__ __launch_bounds__(256)
void reorder2_kernel(const int* __restrict__ src1, const int* __restrict__ dst1,
                     int* __restrict__ cur1, int* __restrict__ edst1,
                     const int* __restrict__ src2, const int* __restrict__ dst2,
                     int* __restrict__ cur2, int* __restrict__ edst2)
{
    int e = blockIdx.x * 256 + threadIdx.x;
    if (e < EE) {
        int s = __ldg(src1 + e);
        int pos = atomicAdd(cur1 + s, 1);
        edst1[pos] = __ldg(dst1 + e);
    } else if (e < 2 * EE) {
        e -= EE;
        int s = __ldg(src2 + e);
        int pos = atomicAdd(cur2 + s, 1);
        edst2[pos] = __ldg(dst2 + e);
    }
}

// ================= aggregate: one warp per node, fp16 rows, MLP=8 =========
// Row = 64 halves = 128B; each lane loads one half2 (4B). fp32 accumulation.
__global__ __launch_bounds__(256)
void agg_kernel(const int* __restrict__ rowptr, const int* __restrict__ deg,
                const int* __restrict__ edst, const __half2* __restrict__ hnei,
                float2* __restrict__ sum, int n)
{
    int warp = (blockIdx.x * 256 + threadIdx.x) >> 5;
    int lane = threadIdx.x & 31;
    if (warp >= n) return;

    int base = __ldg(rowptr + warp);
    int d    = __ldg(deg + warp);

    float2 acc = make_float2(0.f, 0.f);
    for (int j0 = 0; j0 < d; j0 += 32) {
        int e = 0;
        if (j0 + lane < d) e = __ldg(edst + base + j0 + lane);
        int m = min(32, d - j0);
        int jj = 0;
        // 8 independent row-gathers in flight
        for (; jj + 8 <= m; jj += 8) {
            int i0 = __shfl_sync(0xffffffffu, e, jj);
            int i1 = __shfl_sync(0xffffffffu, e, jj + 1);
            int i2 = __shfl_sync(0xffffffffu, e, jj + 2);
            int i3 = __shfl_sync(0xffffffffu, e, jj + 3);
            int i4 = __shfl_sync(0xffffffffu, e, jj + 4);
            int i5 = __shfl_sync(0xffffffffu, e, jj + 5);
            int i6 = __shfl_sync(0xffffffffu, e, jj + 6);
            int i7 = __shfl_sync(0xffffffffu, e, jj + 7);
            __half2 h0 = __ldg(hnei + (long long)i0 * 32 + lane);
            __half2 h1 = __ldg(hnei + (long long)i1 * 32 + lane);
            __half2 h2 = __ldg(hnei + (long long)i2 * 32 + lane);
            __half2 h3 = __ldg(hnei + (long long)i3 * 32 + lane);
            __half2 h4 = __ldg(hnei + (long long)i4 * 32 + lane);
            __half2 h5 = __ldg(hnei + (long long)i5 * 32 + lane);
            __half2 h6 = __ldg(hnei + (long long)i6 * 32 + lane);
            __half2 h7 = __ldg(hnei + (long long)i7 * 32 + lane);
            float2 v0 = __half22float2(h0);
            float2 v1 = __half22float2(h1);
            float2 v2 = __half22float2(h2);
            float2 v3 = __half22float2(h3);
            float2 v4 = __half22float2(h4);
            float2 v5 = __half22float2(h5);
            float2 v6 = __half22float2(h6);
            float2 v7 = __half22float2(h7);
            acc.x += (v0.x + v1.x) + (v2.x + v3.x) + (v4.x + v5.x) + (v6.x + v7.x);
            acc.y += (v0.y + v1.y) + (v2.y + v3.y) + (v4.y + v5.y) + (v6.y + v7.y);
        }
        for (; jj + 4 <= m; jj += 4) {
            int i0 = __shfl_sync(0xffffffffu, e, jj);
            int i1 = __shfl_sync(0xffffffffu, e, jj + 1);
            int i2 = __shfl_sync(0xffffffffu, e, jj + 2);
            int i3 = __shfl_sync(0xffffffffu, e, jj + 3);
            float2 v0 = __half22float2(__ldg(hnei + (long long)i0 * 32 + lane));
            float2 v1 = __half22float2(__ldg(hnei + (long long)i1 * 32 + lane));
            float2 v2 = __half22float2(__ldg(hnei + (long long)i2 * 32 + lane));
            float2 v3 = __half22float2(__ldg(hnei + (long long)i3 * 32 + lane));
            acc.x += (v0.x + v1.x) + (v2.x + v3.x);
            acc.y += (v0.y + v1.y) + (v2.y + v3.y);
        }
        for (; jj < m; jj++) {
            int dd = __shfl_sync(0xffffffffu, e, jj);
            float2 v = __half22float2(__ldg(hnei + (long long)dd * 32 + lane));
            acc.x += v.x;
            acc.y += v.y;
        }
    }
    sum[(long long)warp * 32 + lane] = acc;
}

// ================= fused A-GEMM x2 + epilogue (32KB static smem) =================
__global__ __launch_bounds__(256)
void gemm_epi_kernel(const float* __restrict__ sum1, const float* __restrict__ A0,
                     const float* __restrict__ sum2, const float* __restrict__ A1,
                     const int* __restrict__ deg1, const int* __restrict__ deg2,
                     const float4* __restrict__ hmask, float* __restrict__ out)
{
    constexpr int K4 = HH / 4;           // 16
    __shared__ float4 Xs[64 * K4];       // 16KB
    __shared__ float4 Wt[64 * K4];       // 16KB

    const int t = threadIdx.x;
    const int rowBase = blockIdx.x * 64;
    const int c4  = t & 15;
    const int r0  = (t >> 4) * 4;
    const int swz = c4 & 7;

    float acc1[4][4], acc2[4][4];

    for (int phase = 0; phase < 2; phase++) {
        const float4* X4 = phase ? (const float4*)sum2 : (const float4*)sum1;
        const float* W   = phase ? A1 : A0;
        if (phase) __syncthreads();      // all reads of phase-0 tiles done

#pragma unroll
        for (int it = 0; it < 4; it++) {
            int idx = t + it * 256;      // [0, 1024)
            int r  = idx >> 4;
            int k4 = idx & 15;
            int gr = rowBase + r;
            float4 v = make_float4(0.f, 0.f, 0.f, 0.f);
            if (gr < NN) v = X4[(long long)gr * K4 + k4];
            Xs[idx] = v;
        }
#pragma unroll
        for (int it = 0; it < 16; it++) {
            int idx = t + it * 256;      // [0, 4096)
            int k = idx >> 6;
            int c = idx & 63;
            ((float*)&Wt[c * K4 + ((k >> 2) ^ ((c >> 2) & 7))])[k & 3] = W[idx];
        }
        __syncthreads();

        float (*acc)[4] = phase ? acc2 : acc1;
#pragma unroll
        for (int i = 0; i < 4; i++)
#pragma unroll
            for (int j = 0; j < 4; j++) acc[i][j] = 0.f;

#pragma unroll 4
        for (int k4 = 0; k4 < K4; k4++) {
            float4 xv[4];
#pragma unroll
            for (int i = 0; i < 4; i++) xv[i] = Xs[(r0 + i) * K4 + k4];
#pragma unroll
            for (int j = 0; j < 4; j++) {
                float4 wv = Wt[(c4 * 4 + j) * K4 + (k4 ^ swz)];
#pragma unroll
                for (int i = 0; i < 4; i++)
                    acc[i][j] += xv[i].x * wv.x + xv[i].y * wv.y +
                                 xv[i].z * wv.z + xv[i].w * wv.w;
            }
        }
    }

    // epilogue
    float4* O = (float4*)out;
    const float4* HT = O + 4LL * NN * 16;
#pragma unroll
    for (int i = 0; i < 4; i++) {
        int gr = rowBase + r0 + i;
        if (gr >= NN) continue;
        int d1 = __ldg(deg1 + gr);
        int d2 = __ldg(deg2 + gr);
        float inv1 = d1 > 0 ? 1.f / (float)d1 : 1.f;
        float inv2 = d2 > 0 ? 1.f / (float)d2 : 1.f;
        float4 a1 = make_float4(acc1[i][0] * inv1, acc1[i][1] * inv1,
                                acc1[i][2] * inv1, acc1[i][3] * inv1);
        float4 a2 = make_float4(acc2[i][0] * inv2, acc2[i][1] * inv2,
                                acc2[i][2] * inv2, acc2[i][3] * inv2);
        long long g = (long long)gr * 16 + c4;
        float4 ht = HT[g];
        float4 hm = hmask[g];
        float4 v;
        v = make_float4(ht.x + a1.x, ht.y + a1.y, ht.z + a1.z, ht.w + a1.w);
        O[0LL * NN * 16 + g] = elu4(v);
        v = make_float4(hm.x + a1.x, hm.y + a1.y, hm.z + a1.z, hm.w + a1.w);
        O[1LL * NN * 16 + g] = elu4(v);
        v = make_float4(ht.x + a2.x, ht.y + a2.y, ht.z + a2.z, ht.w + a2.w);
        O[2LL * NN * 16 + g] = elu4(v);
        v = make_float4(hm.x + a2.x, hm.y + a2.y, hm.z + a2.z, hm.w + a2.w);
        O[3LL * NN * 16 + g] = elu4(v);
    }
}

// ================= launch (single stream, no statics, no attribute calls) =========
extern "C" void kernel_launch(void* const* d_in, const int* in_sizes, int n_in,
                              void* d_out, int out_size)
{
    const float* feats0    = (const float*)d_in[0];
    const float* feats1    = (const float*)d_in[1];
    const float* feats2    = (const float*)d_in[2];
    const float* mask_feat = (const float*)d_in[3];
    const int*   src1      = (const int*)d_in[4];
    const int*   dst1      = (const int*)d_in[5];
    const int*   src2      = (const int*)d_in[6];
    const int*   dst2      = (const int*)d_in[7];
    const float* W0        = (const float*)d_in[8];
    const float* b0        = (const float*)d_in[9];
    const float* W1        = (const float*)d_in[10];
    const float* b1        = (const float*)d_in[11];
    const float* W2        = (const float*)d_in[12];
    const float* b2        = (const float*)d_in[13];
    const float* A0        = (const float*)d_in[14];
    const float* A1        = (const float*)d_in[15];

    float* out = (float*)d_out;

    void* fp = nullptr; cudaGetSymbolAddress(&fp, g_fscratch);
    void* ip = nullptr; cudaGetSymbolAddress(&ip, g_iscratch);
    float* F = (float*)fp;
    int*   I = (int*)ip;

    float*   hmask = F + F_HMASK;
    __half*  hnei1 = (__half*)(F + F_HNEI1);
    __half*  hnei2 = (__half*)(F + F_HNEI2);
    float*   sum1  = F + F_SUM1;
    float*   sum2  = F + F_SUM2;

    int* deg1 = I + I_DEG1;
    int* deg2 = I + I_DEG2;
    int* row1 = I + I_ROW1;
    int* row2 = I + I_ROW2;
    int* cur1 = I + I_CUR1;
    int* cur2 = I + I_CUR2;
    int* ctr  = I + I_CTR;
    int* edst1 = I + I_EDST1;
    int* edst2 = I + I_EDST2;

    float* htar = out + 4LL * NN * HH;

    auto cdiv = [](long long a, long long b) { return (int)((a + b - 1) / b); };

    const int NB = cdiv(NN, 256);

    // CSR build chain
    zero_kernel<<<NB, 256>>>(deg1, deg2, ctr);
    hist2_kernel<<<cdiv(2LL * EE, 256), 256>>>(src1, src2, deg1, deg2);
    base2_kernel<<<2 * NB, 256>>>(deg1, row1, cur1, deg2, row2, cur2, ctr, NB);
    reorder2_kernel<<<cdiv(2LL * EE, 256), 256>>>(src1, dst1, cur1, edst1,
                                                  src2, dst2, cur2, edst2);

    // Input GEMMs (+bias +ELU); hnei buffers in fp16, htar/hmask in fp32
    gemm64_kernel<true ><<<cdiv(NN1, 64), 128>>>(feats1,    W1, b1, hnei1, NN1);
    gemm64_kernel<true ><<<cdiv(NN2, 64), 128>>>(feats2,    W2, b2, hnei2, NN2);
    gemm64_kernel<false><<<cdiv(NN,  64), 128>>>(feats0,    W0, b0, htar,  NN);
    gemm64_kernel<false><<<cdiv(NN,  64), 128>>>(mask_feat, W0, b0, hmask, NN);

    // Gather-aggregate (fp16 rows = half the L2 bytes; fp32 accumulation)
    agg_kernel<<<cdiv((long long)NN * 32, 256), 256>>>(row1, deg1, edst1,
                                                       (const __half2*)hnei1, (float2*)sum1, NN);
    agg_kernel<<<cdiv((long long)NN * 32, 256), 256>>>(row2, deg2, edst2,
                                                       (const __half2*)hnei2, (float2*)sum2, NN);

    // Fused A-GEMM x2 + epilogue (divide by deg inside)
    gemm_epi_kernel<<<cdiv(NN, 64), 256>>>(sum1, A0, sum2, A1, deg1, deg2,
                                           (const float4*)hmask, out);
}

// round 16
// speedup vs baseline: 1.2323x; 1.1377x over previous
#include <cuda_runtime.h>
#include <cuda_fp16.h>
#include <math.h>

// Problem constants (fixed by the reference)
constexpr int NN  = 100000;
constexpr int NN1 = 60000;
constexpr int NN2 = 30000;
constexpr int EE  = 1600000;
constexpr int DIN = 128;
constexpr int HH  = 64;

// ---------------- float scratch ----------------
constexpr long long F_HMASK = 0;
constexpr long long F_HNEI1 = F_HMASK + (long long)NN * HH;          // fp16: NN1*HH/2 floats
constexpr long long F_HNEI2 = F_HNEI1 + (long long)NN1 * HH / 2;
constexpr long long F_SUM1  = F_HNEI2 + (long long)NN2 * HH / 2;
constexpr long long F_SUM2  = F_SUM1 + (long long)NN * HH;
constexpr long long F_TOTAL = F_SUM2 + (long long)NN * HH;

__device__ float g_fscratch[F_TOTAL];

// ---------------- int scratch ----------------
constexpr long long I_DEG1 = 0;
constexpr long long I_DEG2 = I_DEG1 + NN;
constexpr long long I_ROW1 = I_DEG2 + NN;
constexpr long long I_ROW2 = I_ROW1 + NN;
constexpr long long I_CUR1 = I_ROW2 + NN;
constexpr long long I_CUR2 = I_CUR1 + NN;
constexpr long long I_CTR  = I_CUR2 + NN;
constexpr long long I_EDST1 = I_CTR + 32;
constexpr long long I_EDST2 = I_EDST1 + EE;
constexpr long long I_TOTAL = I_EDST2 + EE;

__device__ int g_iscratch[I_TOTAL];

// ---------------- helpers ----------------
__device__ __forceinline__ float elu1(float x) { return x > 0.f ? x : expm1f(x); }
__device__ __forceinline__ float4 elu4(float4 v) {
    v.x = elu1(v.x); v.y = elu1(v.y); v.z = elu1(v.z); v.w = elu1(v.w);
    return v;
}

// Packed f32x2 ops (Blackwell): FFMA2 = 2 fp32 FLOP per lane per issue.
__device__ __forceinline__ unsigned long long pk2(float x) {
    unsigned long long r;
    asm("mov.b64 %0, {%1, %1};" : "=l"(r) : "f"(x));
    return r;
}
__device__ __forceinline__ unsigned long long fma2(unsigned long long a,
                                                   unsigned long long b,
                                                   unsigned long long c) {
    unsigned long long d;
    asm("fma.rn.f32x2 %0, %1, %2, %3;" : "=l"(d) : "l"(a), "l"(b), "l"(c));
    return d;
}
__device__ __forceinline__ void unpk2(unsigned long long v, float& lo, float& hi) {
    asm("mov.b64 {%0, %1}, %2;" : "=f"(lo), "=f"(hi) : "l"(v));
}

// ================= input GEMM: Y = elu(X[r,:128] @ W[:,64] + b) =================
// 64x64 tile, 128 threads, 8 rows x 4 cols (2 col-pairs) per thread, f32x2 FMA.
// Wp smem layout: col-pair-interleaved float4 {W[k][2c2],W[k][2c2+1],
// W[k+1][2c2],W[k+1][2c2+1]} at Wp[c2*64 + (k2 ^ (c2>>1))], conflict-free.
template<bool HALF_OUT>
__global__ __launch_bounds__(128)
void gemm64_kernel(const float* __restrict__ X, const float* __restrict__ W,
                   const float* __restrict__ b, void* __restrict__ Yv, int rows)
{
    constexpr int K4 = DIN / 4;          // 32
    __shared__ float4 Xs[64 * K4];       // 32KB
    __shared__ float4 Wp[32 * 64];       // 32KB  (col-pair x k2)

    const int t = threadIdx.x;
    const int rowBase = blockIdx.x * 64;

    const float4* X4 = (const float4*)X;
#pragma unroll
    for (int it = 0; it < 16; it++) {
        int idx = t + it * 128;          // [0, 2048)
        int r  = idx >> 5;
        int k4 = idx & 31;
        int gr = rowBase + r;
        float4 v = make_float4(0.f, 0.f, 0.f, 0.f);
        if (gr < rows) v = X4[(long long)gr * K4 + k4];
        Xs[idx] = v;
    }
    // W [128][64] -> Wp pair-interleaved with swizzle
    float* Wf = (float*)Wp;
#pragma unroll
    for (int it = 0; it < 64; it++) {
        int idx = t + it * 128;          // [0, 8192)
        int k = idx >> 6;                // 0..127
        int c = idx & 63;                // 0..63
        int c2 = c >> 1;                 // col pair 0..31
        int k2 = k >> 1;                 // k pair 0..63
        int k2s = k2 ^ ((c2 >> 1) & 15);
        Wf[(c2 * 64 + k2s) * 4 + (k & 1) * 2 + (c & 1)] = W[idx];
    }
    __syncthreads();

    const int c4 = t & 15;               // output float4 column group
    const int r0 = (t >> 4) * 8;         // 8 rows per thread
    const int swz = c4;                  // = cc>>1 for cc in {2c4, 2c4+1}

    unsigned long long acc2[8][2];
#pragma unroll
    for (int i = 0; i < 8; i++) { acc2[i][0] = 0ull; acc2[i][1] = 0ull; }

#pragma unroll 4
    for (int k4 = 0; k4 < K4; k4++) {
        // 4 wv float4s: (pair p, k2 halves). Each holds 2 column-pair u64s.
        const int cc0 = 2 * c4, cc1 = 2 * c4 + 1;
        float4 w00 = Wp[cc0 * 64 + ((2 * k4)     ^ swz)];
        float4 w01 = Wp[cc0 * 64 + ((2 * k4 + 1) ^ swz)];
        float4 w10 = Wp[cc1 * 64 + ((2 * k4)     ^ swz)];
        float4 w11 = Wp[cc1 * 64 + ((2 * k4 + 1) ^ swz)];
        unsigned long long w00lo = ((unsigned long long*)&w00)[0];
        unsigned long long w00hi = ((unsigned long long*)&w00)[1];
        unsigned long long w01lo = ((unsigned long long*)&w01)[0];
        unsigned long long w01hi = ((unsigned long long*)&w01)[1];
        unsigned long long w10lo = ((unsigned long long*)&w10)[0];
        unsigned long long w10hi = ((unsigned long long*)&w10)[1];
        unsigned long long w11lo = ((unsigned long long*)&w11)[0];
        unsigned long long w11hi = ((unsigned long long*)&w11)[1];

#pragma unroll
        for (int i = 0; i < 8; i++) {
            float4 x = Xs[(r0 + i) * K4 + k4];
            unsigned long long px0 = pk2(x.x);
            unsigned long long px1 = pk2(x.y);
            unsigned long long px2 = pk2(x.z);
            unsigned long long px3 = pk2(x.w);
            acc2[i][0] = fma2(px0, w00lo, acc2[i][0]);
            acc2[i][1] = fma2(px0, w10lo, acc2[i][1]);
            acc2[i][0] = fma2(px1, w00hi, acc2[i][0]);
            acc2[i][1] = fma2(px1, w10hi, acc2[i][1]);
            acc2[i][0] = fma2(px2, w01lo, acc2[i][0]);
            acc2[i][1] = fma2(px2, w11lo, acc2[i][1]);
            acc2[i][0] = fma2(px3, w01hi, acc2[i][0]);
            acc2[i][1] = fma2(px3, w11hi, acc2[i][1]);
        }
    }

    float4 bias = ((const float4*)b)[c4];
#pragma unroll
    for (int i = 0; i < 8; i++) {
        int gr = rowBase + r0 + i;
        if (gr < rows) {
            float4 o;
            unpk2(acc2[i][0], o.x, o.y);
            unpk2(acc2[i][1], o.z, o.w);
            o.x += bias.x; o.y += bias.y; o.z += bias.z; o.w += bias.w;
            o = elu4(o);
            if (HALF_OUT) {
                __half2 h0 = __floats2half2_rn(o.x, o.y);
                __half2 h1 = __floats2half2_rn(o.z, o.w);
                uint2 pkv;
                pkv.x = *(unsigned*)&h0;
                pkv.y = *(unsigned*)&h1;
                ((uint2*)Yv)[(long long)gr * 16 + c4] = pkv;
            } else {
                ((float4*)Yv)[(long long)gr * 16 + c4] = o;
            }
        }
    }
}

// ================= CSR build (proven versions) =================
__global__ __launch_bounds__(256)
void zero_kernel(int* __restrict__ d1, int* __restrict__ d2, int* __restrict__ ctr)
{
    int i = blockIdx.x * 256 + threadIdx.x;
    if (i < NN) { d1[i] = 0; d2[i] = 0; }
    if (i < 2) ctr[i] = 0;
}

__global__ __launch_bounds__(256)
void hist2_kernel(const int* __restrict__ src1, const int* __restrict__ src2,
                  int* __restrict__ deg1, int* __restrict__ deg2)
{
    int e = blockIdx.x * 256 + threadIdx.x;
    if (e < EE)            atomicAdd(deg1 + __ldg(src1 + e), 1);
    else if (e < 2 * EE)   atomicAdd(deg2 + __ldg(src2 + e - EE), 1);
}

__global__ __launch_bounds__(256)
void base2_kernel(const int* __restrict__ deg1, int* __restrict__ row1, int* __restrict__ cur1,
                  const int* __restrict__ deg2, int* __restrict__ row2, int* __restrict__ cur2,
                  int* __restrict__ ctr, int nb)
{
    __shared__ int warpTot[8];
    __shared__ int blockBase;
    int rel = blockIdx.x >= nb;
    const int* deg = rel ? deg2 : deg1;
    int* rowp = rel ? row2 : row1;
    int* cur  = rel ? cur2 : cur1;
    int* counter = ctr + rel;

    int i = (blockIdx.x - rel * nb) * 256 + threadIdx.x;
    int lane = threadIdx.x & 31;
    int wid  = threadIdx.x >> 5;

    int d = (i < NN) ? deg[i] : 0;
    int x = d;
#pragma unroll
    for (int o = 1; o < 32; o <<= 1) {
        int y = __shfl_up_sync(0xffffffffu, x, o);
        if (lane >= o) x += y;
    }
    if (lane == 31) warpTot[wid] = x;
    __syncthreads();
    if (threadIdx.x == 0) {
        int s = 0;
#pragma unroll
        for (int w = 0; w < 8; w++) { int tw = warpTot[w]; warpTot[w] = s; s += tw; }
        blockBase = atomicAdd(counter, s);
    }
    __syncthreads();
    int base = blockBase + warpTot[wid] + x - d;
    if (i < NN) { rowp[i] = base; cur[i] = base; }
}

__global__ __launch_bounds__(256)
void reorder2_kernel(const int* __restrict__ src1, const int* __restrict__ dst1,
                     int* __restrict__ cur1, int* __restrict__ edst1,
                     const int* __restrict__ src2, const int* __restrict__ dst2,
                     int* __restrict__ cur2, int* __restrict__ edst2)
{
    int e = blockIdx.x * 256 + threadIdx.x;
    if (e < EE) {
        int s = __ldg(src1 + e);
        int pos = atomicAdd(cur1 + s, 1);
        edst1[pos] = __ldg(dst1 + e);
    } else if (e < 2 * EE) {
        e -= EE;
        int s = __ldg(src2 + e);
        int pos = atomicAdd(cur2 + s, 1);
        edst2[pos] = __ldg(dst2 + e);
    }
}

// ================= aggregate: one warp per node, fp16 rows, MLP=8 =========
__global__ __launch_bounds__(256)
void agg_kernel(const int* __restrict__ rowptr, const int* __restrict__ deg,
                const int* __restrict__ edst, const __half2* __restrict__ hnei,
                float2* __restrict__ sum, int n)
{
    int warp = (blockIdx.x * 256 + threadIdx.x) >> 5;
    int lane = threadIdx.x & 31;
    if (warp >= n) return;

    int base = __ldg(rowptr + warp);
    int d    = __ldg(deg + warp);

    float2 acc = make_float2(0.f, 0.f);
    for (int j0 = 0; j0 < d; j0 += 32) {
        int e = 0;
        if (j0 + lane < d) e = __ldg(edst + base + j0 + lane);
        int m = min(32, d - j0);
        int jj = 0;
        for (; jj + 8 <= m; jj += 8) {
            int i0 = __shfl_sync(0xffffffffu, e, jj);
            int i1 = __shfl_sync(0xffffffffu, e, jj + 1);
            int i2 = __shfl_sync(0xffffffffu, e, jj + 2);
            int i3 = __shfl_sync(0xffffffffu, e, jj + 3);
            int i4 = __shfl_sync(0xffffffffu, e, jj + 4);
            int i5 = __shfl_sync(0xffffffffu, e, jj + 5);
            int i6 = __shfl_sync(0xffffffffu, e, jj + 6);
            int i7 = __shfl_sync(0xffffffffu, e, jj + 7);
            float2 v0 = __half22float2(__ldg(hnei + (long long)i0 * 32 + lane));
            float2 v1 = __half22float2(__ldg(hnei + (long long)i1 * 32 + lane));
            float2 v2 = __half22float2(__ldg(hnei + (long long)i2 * 32 + lane));
            float2 v3 = __half22float2(__ldg(hnei + (long long)i3 * 32 + lane));
            float2 v4 = __half22float2(__ldg(hnei + (long long)i4 * 32 + lane));
            float2 v5 = __half22float2(__ldg(hnei + (long long)i5 * 32 + lane));
            float2 v6 = __half22float2(__ldg(hnei + (long long)i6 * 32 + lane));
            float2 v7 = __half22float2(__ldg(hnei + (long long)i7 * 32 + lane));
            acc.x += (v0.x + v1.x) + (v2.x + v3.x) + (v4.x + v5.x) + (v6.x + v7.x);
            acc.y += (v0.y + v1.y) + (v2.y + v3.y) + (v4.y + v5.y) + (v6.y + v7.y);
        }
        for (; jj + 4 <= m; jj += 4) {
            int i0 = __shfl_sync(0xffffffffu, e, jj);
            int i1 = __shfl_sync(0xffffffffu, e, jj + 1);
            int i2 = __shfl_sync(0xffffffffu, e, jj + 2);
            int i3 = __shfl_sync(0xffffffffu, e, jj + 3);
            float2 v0 = __half22float2(__ldg(hnei + (long long)i0 * 32 + lane));
            float2 v1 = __half22float2(__ldg(hnei + (long long)i1 * 32 + lane));
            float2 v2 = __half22float2(__ldg(hnei + (long long)i2 * 32 + lane));
            float2 v3 = __half22float2(__ldg(hnei + (long long)i3 * 32 + lane));
            acc.x += (v0.x + v1.x) + (v2.x + v3.x);
            acc.y += (v0.y + v1.y) + (v2.y + v3.y);
        }
        for (; jj < m; jj++) {
            int dd = __shfl_sync(0xffffffffu, e, jj);
            float2 v = __half22float2(__ldg(hnei + (long long)dd * 32 + lane));
            acc.x += v.x;
            acc.y += v.y;
        }
    }
    sum[(long long)warp * 32 + lane] = acc;
}

// ================= fused A-GEMM x2 + epilogue (32KB static smem) =================
__global__ __launch_bounds__(256)
void gemm_epi_kernel(const float* __restrict__ sum1, const float* __restrict__ A0,
                     const float* __restrict__ sum2, const float* __restrict__ A1,
                     const int* __restrict__ deg1, const int* __restrict__ deg2,
                     const float4* __restrict__ hmask, float* __restrict__ out)
{
    constexpr int K4 = HH / 4;           // 16
    __shared__ float4 Xs[64 * K4];       // 16KB
    __shared__ float4 Wt[64 * K4];       // 16KB

    const int t = threadIdx.x;
    const int rowBase = blockIdx.x * 64;
    const int c4  = t & 15;
    const int r0  = (t >> 4) * 4;
    const int swz = c4 & 7;

    float acc1[4][4], acc2[4][4];

    for (int phase = 0; phase < 2; phase++) {
        const float4* X4 = phase ? (const float4*)sum2 : (const float4*)sum1;
        const float* W   = phase ? A1 : A0;
        if (phase) __syncthreads();

#pragma unroll
        for (int it = 0; it < 4; it++) {
            int idx = t + it * 256;
            int r  = idx >> 4;
            int k4 = idx & 15;
            int gr = rowBase + r;
            float4 v = make_float4(0.f, 0.f, 0.f, 0.f);
            if (gr < NN) v = X4[(long long)gr * K4 + k4];
            Xs[idx] = v;
        }
#pragma unroll
        for (int it = 0; it < 16; it++) {
            int idx = t + it * 256;
            int k = idx >> 6;
            int c = idx & 63;
            ((float*)&Wt[c * K4 + ((k >> 2) ^ ((c >> 2) & 7))])[k & 3] = W[idx];
        }
        __syncthreads();

        float (*acc)[4] = phase ? acc2 : acc1;
#pragma unroll
        for (int i = 0; i < 4; i++)
#pragma unroll
            for (int j = 0; j < 4; j++) acc[i][j] = 0.f;

#pragma unroll 4
        for (int k4 = 0; k4 < K4; k4++) {
            float4 xv[4];
#pragma unroll
            for (int i = 0; i < 4; i++) xv[i] = Xs[(r0 + i) * K4 + k4];
#pragma unroll
            for (int j = 0; j < 4; j++) {
                float4 wv = Wt[(c4 * 4 + j) * K4 + (k4 ^ swz)];
#pragma unroll
                for (int i = 0; i < 4; i++)
                    acc[i][j] += xv[i].x * wv.x + xv[i].y * wv.y +
                                 xv[i].z * wv.z + xv[i].w * wv.w;
            }
        }
    }

    // epilogue
    float4* O = (float4*)out;
    const float4* HT = O + 4LL * NN * 16;
#pragma unroll
    for (int i = 0; i < 4; i++) {
        int gr = rowBase + r0 + i;
        if (gr >= NN) continue;
        int d1 = __ldg(deg1 + gr);
        int d2 = __ldg(deg2 + gr);
        float inv1 = d1 > 0 ? 1.f / (float)d1 : 1.f;
        float inv2 = d2 > 0 ? 1.f / (float)d2 : 1.f;
        float4 a1 = make_float4(acc1[i][0] * inv1, acc1[i][1] * inv1,
                                acc1[i][2] * inv1, acc1[i][3] * inv1);
        float4 a2 = make_float4(acc2[i][0] * inv2, acc2[i][1] * inv2,
                                acc2[i][2] * inv2, acc2[i][3] * inv2);
        long long g = (long long)gr * 16 + c4;
        float4 ht = HT[g];
        float4 hm = hmask[g];
        float4 v;
        v = make_float4(ht.x + a1.x, ht.y + a1.y, ht.z + a1.z, ht.w + a1.w);
        O[0LL * NN * 16 + g] = elu4(v);
        v = make_float4(hm.x + a1.x, hm.y + a1.y, hm.z + a1.z, hm.w + a1.w);
        O[1LL * NN * 16 + g] = elu4(v);
        v = make_float4(ht.x + a2.x, ht.y + a2.y, ht.z + a2.z, ht.w + a2.w);
        O[2LL * NN * 16 + g] = elu4(v);
        v = make_float4(hm.x + a2.x, hm.y + a2.y, hm.z + a2.z, hm.w + a2.w);
        O[3LL * NN * 16 + g] = elu4(v);
    }
}

// ================= launch (single stream, no statics, no attribute calls) =========
extern "C" void kernel_launch(void* const* d_in, const int* in_sizes, int n_in,
                              void* d_out, int out_size)
{
    const float* feats0    = (const float*)d_in[0];
    const float* feats1    = (const float*)d_in[1];
    const float* feats2    = (const float*)d_in[2];
    const float* mask_feat = (const float*)d_in[3];
    const int*   src1      = (const int*)d_in[4];
    const int*   dst1      = (const int*)d_in[5];
    const int*   src2      = (const int*)d_in[6];
    const int*   dst2      = (const int*)d_in[7];
    const float* W0        = (const float*)d_in[8];
    const float* b0        = (const float*)d_in[9];
    const float* W1        = (const float*)d_in[10];
    const float* b1        = (const float*)d_in[11];
    const float* W2        = (const float*)d_in[12];
    const float* b2        = (const float*)d_in[13];
    const float* A0        = (const float*)d_in[14];
    const float* A1        = (const float*)d_in[15];

    float* out = (float*)d_out;

    void* fp = nullptr; cudaGetSymbolAddress(&fp, g_fscratch);
    void* ip = nullptr; cudaGetSymbolAddress(&ip, g_iscratch);
    float* F = (float*)fp;
    int*   I = (int*)ip;

    float*   hmask = F + F_HMASK;
    __half*  hnei1 = (__half*)(F + F_HNEI1);
    __half*  hnei2 = (__half*)(F + F_HNEI2);
    float*   sum1  = F + F_SUM1;
    float*   sum2  = F + F_SUM2;

    int* deg1 = I + I_DEG1;
    int* deg2 = I + I_DEG2;
    int* row1 = I + I_ROW1;
    int* row2 = I + I_ROW2;
    int* cur1 = I + I_CUR1;
    int* cur2 = I + I_CUR2;
    int* ctr  = I + I_CTR;
    int* edst1 = I + I_EDST1;
    int* edst2 = I + I_EDST2;

    float* htar = out + 4LL * NN * HH;

    auto cdiv = [](long long a, long long b) { return (int)((a + b - 1) / b); };

    const int NB = cdiv(NN, 256);

    // CSR build chain
    zero_kernel<<<NB, 256>>>(deg1, deg2, ctr);
    hist2_kernel<<<cdiv(2LL * EE, 256), 256>>>(src1, src2, deg1, deg2);
    base2_kernel<<<2 * NB, 256>>>(deg1, row1, cur1, deg2, row2, cur2, ctr, NB);
    reorder2_kernel<<<cdiv(2LL * EE, 256), 256>>>(src1, dst1, cur1, edst1,
                                                  src2, dst2, cur2, edst2);

    // Input GEMMs (+bias +ELU) — f32x2 packed dual-FMA inner loop
    gemm64_kernel<true ><<<cdiv(NN1, 64), 128>>>(feats1,    W1, b1, hnei1, NN1);
    gemm64_kernel<true ><<<cdiv(NN2, 64), 128>>>(feats2,    W2, b2, hnei2, NN2);
    gemm64_kernel<false><<<cdiv(NN,  64), 128>>>(feats0,    W0, b0, htar,  NN);
    gemm64_kernel<false><<<cdiv(NN,  64), 128>>>(mask_feat, W0, b0, hmask, NN);

    // Gather-aggregate (fp16 rows, fp32 accumulation, MLP=8)
    agg_kernel<<<cdiv((long long)NN * 32, 256), 256>>>(row1, deg1, edst1,
                                                       (const __half2*)hnei1, (float2*)sum1, NN);
    agg_kernel<<<cdiv((long long)NN * 32, 256), 256>>>(row2, deg2, edst2,
                                                       (const __half2*)hnei2, (float2*)sum2, NN);

    // Fused A-GEMM x2 + epilogue (divide by deg inside)
    gemm_epi_kernel<<<cdiv(NN, 64), 256>>>(sum1, A0, sum2, A1, deg1, deg2,
                                           (const float4*)hmask, out);
}